// round 11
// baseline (speedup 1.0000x reference)
#include <cuda_runtime.h>
#include <cstdint>
#include <cstddef>

#define N_NODES 1024
#define C_DIM   2048
#define KNB     8
#define KC      8
#define N_EDGES (N_NODES + KC)
#define NSTEPS  (N_NODES - KC)
#define E_PAD   1152   // padded edge-row count (9 * 128)

typedef unsigned long long u64;

// ---------------- scratch (static __device__, zero-initialized) --------------
__device__ float g_xf[N_NODES * C_DIM];
__device__ float g_sq[N_NODES];
__device__ float g_D[N_NODES * N_NODES];
__device__ int   g_neigh[N_NODES * KNB];
__device__ int   g_perm[N_NODES];
__device__ int   g_assign[N_NODES];
__device__ float g_E[E_PAD * C_DIM];    // rows 1032..1151 stay zero
__device__ float g_X1[E_PAD * C_DIM];
__device__ float g_Y[N_NODES * C_DIM];

// ---------------- helpers ----------------------------------------------------
__device__ __forceinline__ float to_tf32(float x) {
    uint32_t r;
    asm("cvt.rna.tf32.f32 %0, %1;" : "=r"(r) : "f"(x));
    return __uint_as_float(r);
}

#define MMA_TF32(d, a, b)                                                     \
    asm volatile(                                                             \
        "mma.sync.aligned.m16n8k8.row.col.f32.tf32.tf32.f32 "                 \
        "{%0,%1,%2,%3}, {%4,%5,%6,%7}, {%8,%9}, {%0,%1,%2,%3};"               \
        : "+f"((d)[0]), "+f"((d)[1]), "+f"((d)[2]), "+f"((d)[3])              \
        : "r"((a)[0]), "r"((a)[1]), "r"((a)[2]), "r"((a)[3]),                 \
          "r"((b)[0]), "r"((b)[1]))

// ---------------- threefry-2x32 (20 rounds) ----------------------------------
__device__ __forceinline__ void threefry2x32(unsigned k0, unsigned k1,
                                             unsigned& x0, unsigned& x1) {
    unsigned ks2 = k0 ^ k1 ^ 0x1BD11BDAu;
    x0 += k0; x1 += k1;
#define TF_R(r) { x0 += x1; x1 = (x1 << (r)) | (x1 >> (32 - (r))); x1 ^= x0; }
    TF_R(13) TF_R(15) TF_R(26) TF_R(6)
    x0 += k1;  x1 += ks2 + 1u;
    TF_R(17) TF_R(29) TF_R(16) TF_R(24)
    x0 += ks2; x1 += k0 + 2u;
    TF_R(13) TF_R(15) TF_R(26) TF_R(6)
    x0 += k0;  x1 += k1 + 3u;
    TF_R(17) TF_R(29) TF_R(16) TF_R(24)
    x0 += k1;  x1 += ks2 + 4u;
    TF_R(13) TF_R(15) TF_R(26) TF_R(6)
    x0 += ks2; x1 += k0 + 5u;
#undef TF_R
}

__global__ void perm_kernel(int* __restrict__ perm) {
    __shared__ u64 keys[N_NODES];
    int tid = threadIdx.x;
    unsigned s0, s1;
    { unsigned a0 = 0u, a1 = 1u; threefry2x32(0u, 42u, a0, a1); s0 = a0; s1 = a1; }
    if (tid < 512) {
        unsigned x0 = 0u, x1 = (unsigned)tid;
        threefry2x32(s0, s1, x0, x1);
        keys[tid] = ((u64)(x0 ^ x1) << 32) | (unsigned)tid;
        unsigned y0 = 0u, y1 = (unsigned)(tid + 512);
        threefry2x32(s0, s1, y0, y1);
        keys[tid + 512] = ((u64)(y0 ^ y1) << 32) | (unsigned)(tid + 512);
    }
    __syncthreads();
    for (int k = 2; k <= N_NODES; k <<= 1) {
        for (int j = k >> 1; j > 0; j >>= 1) {
            int ixj = tid ^ j;
            if (ixj > tid) {
                u64 a = keys[tid], b = keys[ixj];
                bool up = ((tid & k) == 0);
                if ((a > b) == up) { keys[tid] = b; keys[ixj] = a; }
            }
            __syncthreads();
        }
    }
    perm[tid] = (int)(keys[tid] & 0xffffffffull);
}

// ---------------- fp32 SGEMM (GEMM1 only): 128x128, 8x8/thread ---------------
__global__ __launch_bounds__(256) void sgemm_kernel(
    const float* __restrict__ A, const float* __restrict__ B,
    const float* __restrict__ bias, float* __restrict__ C,
    int M, int N, int K) {
    __shared__ float As[16][128];
    __shared__ float Bs[16][128];
    const int tid  = threadIdx.x;
    const int row0 = blockIdx.y * 128;
    const int col0 = blockIdx.x * 128;
    const int am = tid >> 2, ak = (tid & 3) << 2;
    const int bk = tid >> 5, bn = (tid & 31) << 2;
    const int ty = tid >> 4, tx = tid & 15;
    const float4 z4 = make_float4(0.f, 0.f, 0.f, 0.f);

    float4 a0, a1, b0, b1;
    {
        int r = row0 + am;
        a0 = (r      < M) ? *(const float4*)(A + (size_t)r        * K + ak) : z4;
        a1 = (r + 64 < M) ? *(const float4*)(A + (size_t)(r + 64) * K + ak) : z4;
        b0 = *(const float4*)(B + (size_t)bk       * N + col0 + bn);
        b1 = *(const float4*)(B + (size_t)(bk + 8) * N + col0 + bn);
    }
    float acc[8][8] = {};

#define STORE_TILES()                                                         \
    {                                                                         \
        As[ak + 0][am] = a0.x; As[ak + 1][am] = a0.y;                         \
        As[ak + 2][am] = a0.z; As[ak + 3][am] = a0.w;                         \
        As[ak + 0][am + 64] = a1.x; As[ak + 1][am + 64] = a1.y;               \
        As[ak + 2][am + 64] = a1.z; As[ak + 3][am + 64] = a1.w;               \
        *(float4*)&Bs[bk][bn]     = b0;                                       \
        *(float4*)&Bs[bk + 8][bn] = b1;                                       \
    }
#define COMPUTE_TILE()                                                        \
    _Pragma("unroll")                                                         \
    for (int kt = 0; kt < 16; kt++) {                                         \
        float af[8], bf[8];                                                   \
        *(float4*)&af[0] = *(const float4*)&As[kt][ty * 8];                   \
        *(float4*)&af[4] = *(const float4*)&As[kt][ty * 8 + 4];               \
        *(float4*)&bf[0] = *(const float4*)&Bs[kt][tx * 8];                   \
        *(float4*)&bf[4] = *(const float4*)&Bs[kt][tx * 8 + 4];               \
        _Pragma("unroll")                                                     \
        for (int i = 0; i < 8; i++)                                           \
            _Pragma("unroll")                                                 \
            for (int j = 0; j < 8; j++)                                       \
                acc[i][j] = fmaf(af[i], bf[j], acc[i][j]);                    \
    }

    STORE_TILES();
    __syncthreads();
    for (int k0 = 16; k0 < K; k0 += 16) {
        int r = row0 + am;
        a0 = (r      < M) ? *(const float4*)(A + (size_t)r        * K + k0 + ak) : z4;
        a1 = (r + 64 < M) ? *(const float4*)(A + (size_t)(r + 64) * K + k0 + ak) : z4;
        b0 = *(const float4*)(B + (size_t)(k0 + bk)     * N + col0 + bn);
        b1 = *(const float4*)(B + (size_t)(k0 + bk + 8) * N + col0 + bn);
        COMPUTE_TILE();
        __syncthreads();
        STORE_TILES();
        __syncthreads();
    }
    COMPUTE_TILE();

    float4 bias0 = z4, bias1 = z4;
    if (bias) {
        bias0 = *(const float4*)(bias + col0 + tx * 8);
        bias1 = *(const float4*)(bias + col0 + tx * 8 + 4);
    }
#pragma unroll
    for (int i = 0; i < 8; i++) {
        int r = row0 + ty * 8 + i;
        if (r < M) {
            float4 o0 = make_float4(acc[i][0] + bias0.x, acc[i][1] + bias0.y,
                                    acc[i][2] + bias0.z, acc[i][3] + bias0.w);
            float4 o1 = make_float4(acc[i][4] + bias1.x, acc[i][5] + bias1.y,
                                    acc[i][6] + bias1.z, acc[i][7] + bias1.w);
            *(float4*)(C + (size_t)r * N + col0 + tx * 8)     = o0;
            *(float4*)(C + (size_t)r * N + col0 + tx * 8 + 4) = o1;
        }
    }
#undef STORE_TILES
#undef COMPUTE_TILE
}

// ---------------- tf32 mma.sync GEMM: C[M,2048] = A[M,2048] @ B[2048,2048] ---
// base_y lets the launcher split the M dimension across dependency boundaries.
#define AS_STRIDE 36
#define AS_STAGE  (128 * AS_STRIDE)
#define BS_STAGE  (32 * 128)

__global__ __launch_bounds__(256) void mma_gemm_kernel(
    const float* __restrict__ A, const float* __restrict__ B,
    float* __restrict__ C, int base_y) {
    extern __shared__ float sm[];
    float* As = sm;                    // [2][128][36]
    float* Bs = sm + 2 * AS_STAGE;     // [2][32][128]
    const int tid  = threadIdx.x;
    const int lane = tid & 31, wid = tid >> 5;
    const int warp_m = wid >> 2, warp_n = wid & 3;
    const int g = lane >> 2, tig = lane & 3;
    const int row0 = (blockIdx.y + base_y) * 128, col0 = blockIdx.x * 128;

    float acc[4][4][4] = {};
    float4 ar[4], br[4];

#define LOADG(ks)                                                             \
    _Pragma("unroll")                                                         \
    for (int i = 0; i < 4; i++) {                                             \
        int ch = tid * 4 + i;                                                 \
        ar[i] = *(const float4*)(A + (size_t)(row0 + (ch >> 3)) * C_DIM       \
                                 + (ks) * 32 + (ch & 7) * 4);                 \
        br[i] = *(const float4*)(B + (size_t)((ks) * 32 + (ch >> 5)) * C_DIM  \
                                 + col0 + (ch & 31) * 4);                     \
    }

#define STORES(buf)                                                           \
    {                                                                         \
        float* Ab = As + (buf) * AS_STAGE;                                    \
        float* Bb = Bs + (buf) * BS_STAGE;                                    \
        _Pragma("unroll")                                                     \
        for (int i = 0; i < 4; i++) {                                         \
            int ch = tid * 4 + i;                                             \
            float4 v = ar[i];                                                 \
            v.x = to_tf32(v.x); v.y = to_tf32(v.y);                           \
            v.z = to_tf32(v.z); v.w = to_tf32(v.w);                           \
            *(float4*)(Ab + (ch >> 3) * AS_STRIDE + (ch & 7) * 4) = v;        \
            float4 w = br[i];                                                 \
            w.x = to_tf32(w.x); w.y = to_tf32(w.y);                           \
            w.z = to_tf32(w.z); w.w = to_tf32(w.w);                           \
            int kb = ch >> 5, n4 = ch & 31;                                   \
            *(float4*)(Bb + kb * 128 + ((n4 * 4) ^ ((kb & 3) << 3))) = w;     \
        }                                                                     \
    }

#define COMPUTE(buf)                                                          \
    {                                                                         \
        const float* Ab = As + (buf) * AS_STAGE;                              \
        const float* Bb = Bs + (buf) * BS_STAGE;                              \
        _Pragma("unroll")                                                     \
        for (int kk = 0; kk < 4; kk++) {                                      \
            uint32_t af[4][4], bf[4][2];                                      \
            const int k1 = kk * 8 + tig, k2 = kk * 8 + tig + 4;               \
            _Pragma("unroll")                                                 \
            for (int mt = 0; mt < 4; mt++) {                                  \
                int m0 = warp_m * 64 + mt * 16;                               \
                af[mt][0] = __float_as_uint(Ab[(m0 + g)     * AS_STRIDE + k1]); \
                af[mt][1] = __float_as_uint(Ab[(m0 + 8 + g) * AS_STRIDE + k1]); \
                af[mt][2] = __float_as_uint(Ab[(m0 + g)     * AS_STRIDE + k2]); \
                af[mt][3] = __float_as_uint(Ab[(m0 + 8 + g) * AS_STRIDE + k2]); \
            }                                                                 \
            _Pragma("unroll")                                                 \
            for (int nt = 0; nt < 4; nt++) {                                  \
                int n0 = warp_n * 32 + nt * 8;                                \
                bf[nt][0] = __float_as_uint(Bb[k1 * 128 + ((n0 + g) ^ (tig << 3))]); \
                bf[nt][1] = __float_as_uint(Bb[k2 * 128 + ((n0 + g) ^ (tig << 3))]); \
            }                                                                 \
            _Pragma("unroll")                                                 \
            for (int mt = 0; mt < 4; mt++)                                    \
                _Pragma("unroll")                                             \
                for (int nt = 0; nt < 4; nt++)                                \
                    MMA_TF32(acc[mt][nt], af[mt], bf[nt]);                    \
        }                                                                     \
    }

    LOADG(0);
    STORES(0);
    __syncthreads();
    for (int ks = 0; ks < 64; ks++) {
        const int cur = ks & 1;
        if (ks < 63) { LOADG(ks + 1); }
        COMPUTE(cur);
        if (ks < 63) { STORES(cur ^ 1); }
        __syncthreads();
    }

#pragma unroll
    for (int mt = 0; mt < 4; mt++) {
#pragma unroll
        for (int nt = 0; nt < 4; nt++) {
            int r  = row0 + warp_m * 64 + mt * 16 + g;
            int cc = col0 + warp_n * 32 + nt * 8 + tig * 2;
            *(float2*)(C + (size_t)r * C_DIM + cc) =
                make_float2(acc[mt][nt][0], acc[mt][nt][1]);
            *(float2*)(C + (size_t)(r + 8) * C_DIM + cc) =
                make_float2(acc[mt][nt][2], acc[mt][nt][3]);
        }
    }
#undef LOADG
#undef STORES
#undef COMPUTE
}

// ---------------- row squared norms ------------------------------------------
__global__ void rowsq_kernel(const float* __restrict__ xf, float* __restrict__ sq) {
    int row = blockIdx.x, tid = threadIdx.x;
    const float* x = xf + (size_t)row * C_DIM;
    float s = 0.f;
    for (int c = tid; c < C_DIM; c += 256) { float v = x[c]; s = fmaf(v, v, s); }
    for (int off = 16; off; off >>= 1) s += __shfl_xor_sync(0xffffffffu, s, off);
    __shared__ float r[8];
    if ((tid & 31) == 0) r[tid >> 5] = s;
    __syncthreads();
    if (tid == 0) { float t = 0.f; for (int w = 0; w < 8; w++) t += r[w]; sq[row] = t; }
}

// ---------------- pairwise distance: 128x64 tile, 8x4/thread -----------------
__global__ __launch_bounds__(256) void dist_kernel(
    const float* __restrict__ xf, const float* __restrict__ sq,
    float* __restrict__ D) {
    __shared__ float As[16][128];
    __shared__ float Bs[16][64];
    const int tid  = threadIdx.x;
    const int row0 = blockIdx.y * 128;
    const int col0 = blockIdx.x * 64;
    const int am = tid >> 2, ak = (tid & 3) << 2;
    const int ty = tid >> 4, tx = tid & 15;

    float4 a0, a1, b0;
    {
        a0 = *(const float4*)(xf + (size_t)(row0 + am)      * C_DIM + ak);
        a1 = *(const float4*)(xf + (size_t)(row0 + am + 64) * C_DIM + ak);
        b0 = *(const float4*)(xf + (size_t)(col0 + am)      * C_DIM + ak);
    }
    float acc[8][4] = {};

#define D_STORE()                                                             \
    {                                                                         \
        As[ak + 0][am] = a0.x; As[ak + 1][am] = a0.y;                         \
        As[ak + 2][am] = a0.z; As[ak + 3][am] = a0.w;                         \
        As[ak + 0][am + 64] = a1.x; As[ak + 1][am + 64] = a1.y;               \
        As[ak + 2][am + 64] = a1.z; As[ak + 3][am + 64] = a1.w;               \
        if (am < 64) {                                                        \
            Bs[ak + 0][am] = b0.x; Bs[ak + 1][am] = b0.y;                     \
            Bs[ak + 2][am] = b0.z; Bs[ak + 3][am] = b0.w;                     \
        }                                                                     \
    }
#define D_COMPUTE()                                                           \
    _Pragma("unroll")                                                         \
    for (int kt = 0; kt < 16; kt++) {                                         \
        float af[8], bf[4];                                                   \
        *(float4*)&af[0] = *(const float4*)&As[kt][ty * 8];                   \
        *(float4*)&af[4] = *(const float4*)&As[kt][ty * 8 + 4];               \
        *(float4*)&bf[0] = *(const float4*)&Bs[kt][tx * 4];                   \
        _Pragma("unroll")                                                     \
        for (int i = 0; i < 8; i++)                                           \
            _Pragma("unroll")                                                 \
            for (int j = 0; j < 4; j++)                                       \
                acc[i][j] = fmaf(af[i], bf[j], acc[i][j]);                    \
    }

    D_STORE();
    __syncthreads();
    for (int k0 = 16; k0 < C_DIM; k0 += 16) {
        a0 = *(const float4*)(xf + (size_t)(row0 + am)      * C_DIM + k0 + ak);
        a1 = *(const float4*)(xf + (size_t)(row0 + am + 64) * C_DIM + k0 + ak);
        b0 = *(const float4*)(xf + (size_t)(col0 + am)      * C_DIM + k0 + ak);
        D_COMPUTE();
        __syncthreads();
        D_STORE();
        __syncthreads();
    }
    D_COMPUTE();

#pragma unroll
    for (int i = 0; i < 8; i++) {
        int r = row0 + ty * 8 + i;
        float sqr = sq[r];
        float4 o;
        int c = col0 + tx * 4;
        o.x = sqrtf(fmaxf(sqr + sq[c + 0] - 2.f * acc[i][0], 0.f));
        o.y = sqrtf(fmaxf(sqr + sq[c + 1] - 2.f * acc[i][1], 0.f));
        o.z = sqrtf(fmaxf(sqr + sq[c + 2] - 2.f * acc[i][2], 0.f));
        o.w = sqrtf(fmaxf(sqr + sq[c + 3] - 2.f * acc[i][3], 0.f));
        *(float4*)(D + (size_t)r * N_NODES + c) = o;
    }
#undef D_STORE
#undef D_COMPUTE
}

// ---------------- kNN: 8 smallest per row (diag excluded), redux merge -------
__global__ void knn_kernel(const float* __restrict__ D, int* __restrict__ neigh) {
    int gw = (blockIdx.x * blockDim.x + threadIdx.x) >> 5;
    int lane = threadIdx.x & 31;
    if (gw >= N_NODES) return;
    const float* row = D + (size_t)gw * N_NODES;
    float val[8]; int idx[8];
#pragma unroll
    for (int r = 0; r < 8; r++) { val[r] = __int_as_float(0x7f800000); idx[r] = 0; }
    for (int j = lane; j < N_NODES; j += 32) {
        if (j == gw) continue;
        float v = row[j];
        if (v < val[7]) {
            val[7] = v; idx[7] = j;
#pragma unroll
            for (int p = 7; p > 0; p--) {
                if (val[p] < val[p - 1]) {
                    float tv = val[p]; val[p] = val[p - 1]; val[p - 1] = tv;
                    int   ti = idx[p]; idx[p] = idx[p - 1]; idx[p - 1] = ti;
                }
            }
        }
    }
    int ptr = 0;
#pragma unroll
    for (int r = 0; r < 8; r++) {
        unsigned vb = (ptr < 8) ? __float_as_uint(val[ptr]) : 0x7f800000u;
        unsigned vm = __reduce_min_sync(0xffffffffu, vb);
        unsigned mi = (ptr < 8 && vb == vm) ? (unsigned)idx[ptr] : 0x7fffffffu;
        unsigned im = __reduce_min_sync(0xffffffffu, mi);
        if (lane == 0) neigh[gw * KNB + r] = (int)im;
        if (ptr < 8 && vb == vm && (unsigned)idx[ptr] == im) ptr++;
    }
}

// ---------------- sequential k-means: 8 warps, 1 barrier/step ----------------
// thread t owns i = j*256 + t (j = 0..3). Every warp redundantly finalizes the
// previous centroid update and selects the cluster. BOTH cross-step shared
// structures are double-buffered by step parity:
//   red    : write buf step&1, read buf (step+1)&1 (= previous step's buffer)
//   Drow_sh: read buf step&1, rotate-write buf (step+1)&1
__global__ __launch_bounds__(256) void kmeans_kernel(
    const float* __restrict__ D, const int* __restrict__ perm,
    int* __restrict__ assign_out) {
    __shared__ float S[KC * N_NODES];       // 32KB, owner-thread only
    __shared__ float Drow_sh[2][N_NODES];   // 8KB, parity double-buffered
    __shared__ int   sperm[N_NODES];        // 4KB, read-only after init
    __shared__ u64   red[2][8];             // parity double-buffered
    const int t = threadIdx.x;
    const int lane = t & 31;
    const int wid = t >> 5;
    const float INF = __int_as_float(0x7f800000);
    const unsigned FULL = 0xffffffffu;

    for (int i = t; i < N_NODES; i += 256) sperm[i] = perm[i];
    __syncthreads();
    int mycent = (lane < KC) ? sperm[lane] : 0;   // replicated in every warp
    for (int c = 0; c < KC; c++) {
        const float* row = D + (size_t)sperm[c] * N_NODES;
#pragma unroll
        for (int j = 0; j < 4; j++)
            S[c * N_NODES + j * 256 + t] = row[j * 256 + t];
    }
    // membership nibbles: slot j (global i = j*256+t), value = cluster+1
    unsigned nib = 0u;
    for (int c = 0; c < KC; c++) {
        int p = sperm[c];
        if ((p & 255) == t) nib |= (unsigned)(c + 1) << ((p >> 8) * 4);
    }
    float cur[4];
    {
        const float* row = D + (size_t)sperm[KC] * N_NODES;
#pragma unroll
        for (int j = 0; j < 4; j++) {
            cur[j] = row[j * 256 + t];
            Drow_sh[0][j * 256 + t] = cur[j];
        }
    }
    int c_prev = -1;   // warp-uniform
    __syncthreads();

    for (int step = 0; step < NSTEPS; step++) {
        const int ni = sperm[KC + step];
        const int rb = step & 1;           // read buffer (Drow_sh + red write)
        const int wb = rb ^ 1;             // write buffer for next step's row
        // finalize previous step's centroid (redundant in all 8 warps)
        if (step > 0) {
            u64 rv = (lane < 8) ? red[wb][lane] : ~0ull;   // prev step's buffer
            unsigned hv = (unsigned)(rv >> 32);
            unsigned hm = __reduce_min_sync(FULL, hv);
            unsigned cand = (hv == hm) ? (unsigned)(rv & 0xffffffffull) : 0xffffffffu;
            unsigned newc = __reduce_min_sync(FULL, cand);
            if (lane == c_prev) mycent = (int)newc;
        }
        // select nearest centroid for ni (redundant; first-index tiebreak)
        unsigned cb = (lane < KC) ? __float_as_uint(Drow_sh[rb][mycent]) : 0x7f800000u;
        unsigned cm = __reduce_min_sync(FULL, cb);
        unsigned cmask = __ballot_sync(FULL, cb == cm);
        const int c = __ffs(cmask) - 1;
        c_prev = c;
        const unsigned tgt = (unsigned)(c + 1);
        // prefetch next node's D row (coalesced)
        float nxt[4];
        {
            const int nn = sperm[KC + ((step + 1 < NSTEPS) ? step + 1 : step)];
            const float* row = D + (size_t)nn * N_NODES;
#pragma unroll
            for (int j = 0; j < 4; j++) nxt[j] = row[j * 256 + t];
        }
        // S[c] += Drow; masked min (argmin of S over members == argmin of mean)
        float* Sc = S + c * N_NODES;
        float vv[4];
#pragma unroll
        for (int j = 0; j < 4; j++) {
            float s = Sc[j * 256 + t] + cur[j];
            Sc[j * 256 + t] = s;
            bool memb = (((nib >> (j * 4)) & 15u) == tgt) | ((j * 256 + t) == ni);
            vv[j] = memb ? s : INF;
        }
        float m0 = fminf(vv[0], vv[2]), m1 = fminf(vv[1], vv[3]);
        const float minv = fminf(m0, m1);
        unsigned msk = 0u;
#pragma unroll
        for (int j = 0; j < 4; j++) msk |= (vv[j] == minv) ? (1u << j) : 0u;
        const int besti = (__ffs(msk) - 1) * 256 + t;
        // per-warp argmin (value, then smallest global index)
        unsigned bb = __float_as_uint(minv);
        unsigned bm = __reduce_min_sync(FULL, bb);
        unsigned cand2 = (bb == bm) ? (unsigned)besti : 0xffffffffu;
        unsigned im = __reduce_min_sync(FULL, cand2);
        if (lane == 0) red[rb][wid] = ((u64)bm << 32) | im;
        // record assignment of ni
        if ((ni & 255) == t) nib |= tgt << ((ni >> 8) * 4);
        // rotate prefetched row into the OTHER buffer (read next step)
#pragma unroll
        for (int j = 0; j < 4; j++) {
            Drow_sh[wb][j * 256 + t] = nxt[j];
            cur[j] = nxt[j];
        }
        __syncthreads();   // red[rb] + Drow_sh[wb] visible for next step
    }
#pragma unroll
    for (int j = 0; j < 4; j++)
        assign_out[j * 256 + t] = (int)((nib >> (j * 4)) & 15u) - 1;
}

// ---------------- E[e] = sum_{v in neigh(e)} xf[v] ---------------------------
__global__ void agg_local_kernel(const float* __restrict__ xf, const int* __restrict__ neigh,
                                 float* __restrict__ E) {
    int e = blockIdx.x;
    int nb[KNB];
#pragma unroll
    for (int j = 0; j < KNB; j++) nb[j] = neigh[e * KNB + j];
    for (int c = threadIdx.x; c < C_DIM; c += 256) {
        float s = 0.f;
#pragma unroll
        for (int j = 0; j < KNB; j++) s += xf[(size_t)nb[j] * C_DIM + c];
        E[(size_t)e * C_DIM + c] = s;
    }
}

// ---------------- E[n+c] = sum_{assign[v]==c} xf[v] --------------------------
__global__ void agg_global_kernel(const float* __restrict__ xf, const int* __restrict__ assign_,
                                  float* __restrict__ E) {
    __shared__ int sa[N_NODES];
    int tid = threadIdx.x;
    for (int i = tid; i < N_NODES; i += 256) sa[i] = assign_[i];
    __syncthreads();
    int c = blockIdx.x;
    int col = blockIdx.y * 256 + tid;
    float s = 0.f;
    for (int i = 0; i < N_NODES; i++)
        if (sa[i] == c) s += xf[(size_t)i * C_DIM + col];
    E[(size_t)(N_NODES + c) * C_DIM + col] = s;
}

// ---------------- Y[v] = sum_{e: v in neigh(e)} X1[e] + X1[n+assign[v]] ------
__global__ void agg_out_kernel(const float* __restrict__ X1, const int* __restrict__ neigh,
                               const int* __restrict__ assign_, float* __restrict__ Y) {
    int v = blockIdx.x;
    __shared__ int list[N_NODES];
    __shared__ int cnt_s;
    int tid = threadIdx.x, lane = tid & 31, wid = tid >> 5;
    if (wid == 0) {
        int cnt = 0;
        for (int base = 0; base < N_NODES; base += 32) {
            int e = base + lane;
            const int4* p = (const int4*)(neigh + e * KNB);
            int4 q0 = p[0], q1 = p[1];
            bool m = (q0.x == v) | (q0.y == v) | (q0.z == v) | (q0.w == v) |
                     (q1.x == v) | (q1.y == v) | (q1.z == v) | (q1.w == v);
            unsigned msk = __ballot_sync(0xffffffffu, m);
            if (m) list[cnt + __popc(msk & ((1u << lane) - 1u))] = e;
            cnt += __popc(msk);
        }
        if (lane == 0) cnt_s = cnt;
    }
    __syncthreads();
    int cnt = cnt_s;
    int ge = N_NODES + assign_[v];
    float s[8];
#pragma unroll
    for (int w = 0; w < 8; w++) s[w] = X1[(size_t)ge * C_DIM + tid + w * 256];
    for (int t = 0; t < cnt; t++) {
        const float* xr = X1 + (size_t)list[t] * C_DIM;
#pragma unroll
        for (int w = 0; w < 8; w++) s[w] += xr[tid + w * 256];
    }
#pragma unroll
    for (int w = 0; w < 8; w++) Y[(size_t)v * C_DIM + tid + w * 256] = s[w];
}

// ---------------- host launcher ----------------------------------------------
extern "C" void kernel_launch(void* const* d_in, const int* in_sizes, int n_in,
                              void* d_out, int out_size) {
    const float* x0  = (const float*)d_in[0];
    const float* wfc = (const float*)d_in[1];
    const float* bfc = (const float*)d_in[2];
    const float* w1  = (const float*)d_in[3];
    const float* w2  = (const float*)d_in[4];
    float* out = (float*)d_out;

    float *xf, *sq, *D, *E, *X1, *Y;
    int *neigh, *perm, *assign_;
    cudaGetSymbolAddress((void**)&xf,      g_xf);
    cudaGetSymbolAddress((void**)&sq,      g_sq);
    cudaGetSymbolAddress((void**)&D,       g_D);
    cudaGetSymbolAddress((void**)&neigh,   g_neigh);
    cudaGetSymbolAddress((void**)&perm,    g_perm);
    cudaGetSymbolAddress((void**)&assign_, g_assign);
    cudaGetSymbolAddress((void**)&E,       g_E);
    cudaGetSymbolAddress((void**)&X1,      g_X1);
    cudaGetSymbolAddress((void**)&Y,       g_Y);

    // one-time setup of the side stream + fork/join events (created on the
    // first, uncaptured correctness call; reused during graph capture)
    static cudaStream_t s2 = nullptr;
    static cudaEvent_t evStart = nullptr, evD = nullptr, evK = nullptr;
    if (s2 == nullptr) {
        cudaStreamCreateWithFlags(&s2, cudaStreamNonBlocking);
        cudaEventCreateWithFlags(&evStart, cudaEventDisableTiming);
        cudaEventCreateWithFlags(&evD,     cudaEventDisableTiming);
        cudaEventCreateWithFlags(&evK,     cudaEventDisableTiming);
    }

    const size_t dynsmem = (2 * AS_STAGE + 2 * BS_STAGE) * sizeof(float);  // 69632
    cudaFuncSetAttribute(mma_gemm_kernel,
                         cudaFuncAttributeMaxDynamicSharedMemorySize, (int)dynsmem);

    // fork s2 at the very start (perm is independent of everything)
    cudaEventRecord(evStart, 0);
    cudaStreamWaitEvent(s2, evStart, 0);
    perm_kernel<<<1, 1024, 0, s2>>>(perm);

    // main stream: x_f -> D
    sgemm_kernel<<<dim3(C_DIM / 128, N_NODES / 128), 256>>>(x0, wfc, bfc, xf,
                                                            N_NODES, C_DIM, C_DIM);
    rowsq_kernel<<<N_NODES, 256>>>(xf, sq);
    dist_kernel<<<dim3(N_NODES / 64, N_NODES / 128), 256>>>(xf, sq, D);
    cudaEventRecord(evD, 0);

    // side stream: kmeans (needs D + perm), ~380us on one SM
    cudaStreamWaitEvent(s2, evD, 0);
    kmeans_kernel<<<1, 256, 0, s2>>>(D, perm, assign_);
    cudaEventRecord(evK, s2);

    // main stream, concurrent with kmeans: knn -> local aggregation -> GEMM2
    // over the local edge rows (0..1023, i.e. the first 8 row-blocks)
    knn_kernel<<<N_NODES / 8, 256>>>(D, neigh);
    agg_local_kernel<<<N_NODES, 256>>>(xf, neigh, E);
    mma_gemm_kernel<<<dim3(C_DIM / 128, 8), 256, dynsmem>>>(E, w1, X1, 0);

    // join: everything below needs the kmeans assignments
    cudaStreamWaitEvent(0, evK, 0);
    agg_global_kernel<<<dim3(KC, C_DIM / 256), 256>>>(xf, assign_, E);
    mma_gemm_kernel<<<dim3(C_DIM / 128, 1), 256, dynsmem>>>(E, w1, X1, 8);
    agg_out_kernel<<<N_NODES, 256>>>(X1, neigh, assign_, Y);
    mma_gemm_kernel<<<dim3(C_DIM / 128, N_NODES / 128), 256, dynsmem>>>(Y, w2, out, 0);
}

// round 12
// speedup vs baseline: 1.0579x; 1.0579x over previous
#include <cuda_runtime.h>
#include <cstdint>
#include <cstddef>

#define N_NODES 1024
#define C_DIM   2048
#define KNB     8
#define KC      8
#define N_EDGES (N_NODES + KC)
#define NSTEPS  (N_NODES - KC)
#define E_PAD   1152   // padded edge-row count (9 * 128)

typedef unsigned long long u64;

// ---------------- scratch (static __device__, zero-initialized) --------------
__device__ float g_xf[N_NODES * C_DIM];
__device__ float g_sq[N_NODES];
__device__ float g_D[N_NODES * N_NODES];
__device__ int   g_neigh[N_NODES * KNB];
__device__ int   g_perm[N_NODES];
__device__ int   g_assign[N_NODES];
__device__ float g_E[E_PAD * C_DIM];    // rows 1032..1151 stay zero
__device__ float g_X1[E_PAD * C_DIM];
__device__ float g_Y[N_NODES * C_DIM];

// ---------------- helpers ----------------------------------------------------
__device__ __forceinline__ float to_tf32(float x) {
    uint32_t r;
    asm("cvt.rna.tf32.f32 %0, %1;" : "=r"(r) : "f"(x));
    return __uint_as_float(r);
}

#define MMA_TF32(d, a, b)                                                     \
    asm volatile(                                                             \
        "mma.sync.aligned.m16n8k8.row.col.f32.tf32.tf32.f32 "                 \
        "{%0,%1,%2,%3}, {%4,%5,%6,%7}, {%8,%9}, {%0,%1,%2,%3};"               \
        : "+f"((d)[0]), "+f"((d)[1]), "+f"((d)[2]), "+f"((d)[3])              \
        : "r"((a)[0]), "r"((a)[1]), "r"((a)[2]), "r"((a)[3]),                 \
          "r"((b)[0]), "r"((b)[1]))

// ---------------- threefry-2x32 (20 rounds) ----------------------------------
__device__ __forceinline__ void threefry2x32(unsigned k0, unsigned k1,
                                             unsigned& x0, unsigned& x1) {
    unsigned ks2 = k0 ^ k1 ^ 0x1BD11BDAu;
    x0 += k0; x1 += k1;
#define TF_R(r) { x0 += x1; x1 = (x1 << (r)) | (x1 >> (32 - (r))); x1 ^= x0; }
    TF_R(13) TF_R(15) TF_R(26) TF_R(6)
    x0 += k1;  x1 += ks2 + 1u;
    TF_R(17) TF_R(29) TF_R(16) TF_R(24)
    x0 += ks2; x1 += k0 + 2u;
    TF_R(13) TF_R(15) TF_R(26) TF_R(6)
    x0 += k0;  x1 += k1 + 3u;
    TF_R(17) TF_R(29) TF_R(16) TF_R(24)
    x0 += k1;  x1 += ks2 + 4u;
    TF_R(13) TF_R(15) TF_R(26) TF_R(6)
    x0 += ks2; x1 += k0 + 5u;
#undef TF_R
}

__global__ void perm_kernel(int* __restrict__ perm) {
    __shared__ u64 keys[N_NODES];
    int tid = threadIdx.x;
    unsigned s0, s1;
    { unsigned a0 = 0u, a1 = 1u; threefry2x32(0u, 42u, a0, a1); s0 = a0; s1 = a1; }
    if (tid < 512) {
        unsigned x0 = 0u, x1 = (unsigned)tid;
        threefry2x32(s0, s1, x0, x1);
        keys[tid] = ((u64)(x0 ^ x1) << 32) | (unsigned)tid;
        unsigned y0 = 0u, y1 = (unsigned)(tid + 512);
        threefry2x32(s0, s1, y0, y1);
        keys[tid + 512] = ((u64)(y0 ^ y1) << 32) | (unsigned)(tid + 512);
    }
    __syncthreads();
    for (int k = 2; k <= N_NODES; k <<= 1) {
        for (int j = k >> 1; j > 0; j >>= 1) {
            int ixj = tid ^ j;
            if (ixj > tid) {
                u64 a = keys[tid], b = keys[ixj];
                bool up = ((tid & k) == 0);
                if ((a > b) == up) { keys[tid] = b; keys[ixj] = a; }
            }
            __syncthreads();
        }
    }
    perm[tid] = (int)(keys[tid] & 0xffffffffull);
}

// ---------------- fp32 SGEMM (GEMM1 only): 128x128, 8x8/thread ---------------
__global__ __launch_bounds__(256) void sgemm_kernel(
    const float* __restrict__ A, const float* __restrict__ B,
    const float* __restrict__ bias, float* __restrict__ C,
    int M, int N, int K) {
    __shared__ float As[16][128];
    __shared__ float Bs[16][128];
    const int tid  = threadIdx.x;
    const int row0 = blockIdx.y * 128;
    const int col0 = blockIdx.x * 128;
    const int am = tid >> 2, ak = (tid & 3) << 2;
    const int bk = tid >> 5, bn = (tid & 31) << 2;
    const int ty = tid >> 4, tx = tid & 15;
    const float4 z4 = make_float4(0.f, 0.f, 0.f, 0.f);

    float4 a0, a1, b0, b1;
    {
        int r = row0 + am;
        a0 = (r      < M) ? *(const float4*)(A + (size_t)r        * K + ak) : z4;
        a1 = (r + 64 < M) ? *(const float4*)(A + (size_t)(r + 64) * K + ak) : z4;
        b0 = *(const float4*)(B + (size_t)bk       * N + col0 + bn);
        b1 = *(const float4*)(B + (size_t)(bk + 8) * N + col0 + bn);
    }
    float acc[8][8] = {};

#define STORE_TILES()                                                         \
    {                                                                         \
        As[ak + 0][am] = a0.x; As[ak + 1][am] = a0.y;                         \
        As[ak + 2][am] = a0.z; As[ak + 3][am] = a0.w;                         \
        As[ak + 0][am + 64] = a1.x; As[ak + 1][am + 64] = a1.y;               \
        As[ak + 2][am + 64] = a1.z; As[ak + 3][am + 64] = a1.w;               \
        *(float4*)&Bs[bk][bn]     = b0;                                       \
        *(float4*)&Bs[bk + 8][bn] = b1;                                       \
    }
#define COMPUTE_TILE()                                                        \
    _Pragma("unroll")                                                         \
    for (int kt = 0; kt < 16; kt++) {                                         \
        float af[8], bf[8];                                                   \
        *(float4*)&af[0] = *(const float4*)&As[kt][ty * 8];                   \
        *(float4*)&af[4] = *(const float4*)&As[kt][ty * 8 + 4];               \
        *(float4*)&bf[0] = *(const float4*)&Bs[kt][tx * 8];                   \
        *(float4*)&bf[4] = *(const float4*)&Bs[kt][tx * 8 + 4];               \
        _Pragma("unroll")                                                     \
        for (int i = 0; i < 8; i++)                                           \
            _Pragma("unroll")                                                 \
            for (int j = 0; j < 8; j++)                                       \
                acc[i][j] = fmaf(af[i], bf[j], acc[i][j]);                    \
    }

    STORE_TILES();
    __syncthreads();
    for (int k0 = 16; k0 < K; k0 += 16) {
        int r = row0 + am;
        a0 = (r      < M) ? *(const float4*)(A + (size_t)r        * K + k0 + ak) : z4;
        a1 = (r + 64 < M) ? *(const float4*)(A + (size_t)(r + 64) * K + k0 + ak) : z4;
        b0 = *(const float4*)(B + (size_t)(k0 + bk)     * N + col0 + bn);
        b1 = *(const float4*)(B + (size_t)(k0 + bk + 8) * N + col0 + bn);
        COMPUTE_TILE();
        __syncthreads();
        STORE_TILES();
        __syncthreads();
    }
    COMPUTE_TILE();

    float4 bias0 = z4, bias1 = z4;
    if (bias) {
        bias0 = *(const float4*)(bias + col0 + tx * 8);
        bias1 = *(const float4*)(bias + col0 + tx * 8 + 4);
    }
#pragma unroll
    for (int i = 0; i < 8; i++) {
        int r = row0 + ty * 8 + i;
        if (r < M) {
            float4 o0 = make_float4(acc[i][0] + bias0.x, acc[i][1] + bias0.y,
                                    acc[i][2] + bias0.z, acc[i][3] + bias0.w);
            float4 o1 = make_float4(acc[i][4] + bias1.x, acc[i][5] + bias1.y,
                                    acc[i][6] + bias1.z, acc[i][7] + bias1.w);
            *(float4*)(C + (size_t)r * N + col0 + tx * 8)     = o0;
            *(float4*)(C + (size_t)r * N + col0 + tx * 8 + 4) = o1;
        }
    }
#undef STORE_TILES
#undef COMPUTE_TILE
}

// ---------------- tf32 mma.sync GEMM: C[M,2048] = A[M,2048] @ B[2048,2048] ---
#define AS_STRIDE 36
#define AS_STAGE  (128 * AS_STRIDE)
#define BS_STAGE  (32 * 128)

__global__ __launch_bounds__(256) void mma_gemm_kernel(
    const float* __restrict__ A, const float* __restrict__ B,
    float* __restrict__ C) {
    extern __shared__ float sm[];
    float* As = sm;                    // [2][128][36]
    float* Bs = sm + 2 * AS_STAGE;     // [2][32][128]
    const int tid  = threadIdx.x;
    const int lane = tid & 31, wid = tid >> 5;
    const int warp_m = wid >> 2, warp_n = wid & 3;
    const int g = lane >> 2, tig = lane & 3;
    const int row0 = blockIdx.y * 128, col0 = blockIdx.x * 128;

    float acc[4][4][4] = {};
    float4 ar[4], br[4];

#define LOADG(ks)                                                             \
    _Pragma("unroll")                                                         \
    for (int i = 0; i < 4; i++) {                                             \
        int ch = tid * 4 + i;                                                 \
        ar[i] = *(const float4*)(A + (size_t)(row0 + (ch >> 3)) * C_DIM       \
                                 + (ks) * 32 + (ch & 7) * 4);                 \
        br[i] = *(const float4*)(B + (size_t)((ks) * 32 + (ch >> 5)) * C_DIM  \
                                 + col0 + (ch & 31) * 4);                     \
    }

#define STORES(buf)                                                           \
    {                                                                         \
        float* Ab = As + (buf) * AS_STAGE;                                    \
        float* Bb = Bs + (buf) * BS_STAGE;                                    \
        _Pragma("unroll")                                                     \
        for (int i = 0; i < 4; i++) {                                         \
            int ch = tid * 4 + i;                                             \
            float4 v = ar[i];                                                 \
            v.x = to_tf32(v.x); v.y = to_tf32(v.y);                           \
            v.z = to_tf32(v.z); v.w = to_tf32(v.w);                           \
            *(float4*)(Ab + (ch >> 3) * AS_STRIDE + (ch & 7) * 4) = v;        \
            float4 w = br[i];                                                 \
            w.x = to_tf32(w.x); w.y = to_tf32(w.y);                           \
            w.z = to_tf32(w.z); w.w = to_tf32(w.w);                           \
            int kb = ch >> 5, n4 = ch & 31;                                   \
            *(float4*)(Bb + kb * 128 + ((n4 * 4) ^ ((kb & 3) << 3))) = w;     \
        }                                                                     \
    }

#define COMPUTE(buf)                                                          \
    {                                                                         \
        const float* Ab = As + (buf) * AS_STAGE;                              \
        const float* Bb = Bs + (buf) * BS_STAGE;                              \
        _Pragma("unroll")                                                     \
        for (int kk = 0; kk < 4; kk++) {                                      \
            uint32_t af[4][4], bf[4][2];                                      \
            const int k1 = kk * 8 + tig, k2 = kk * 8 + tig + 4;               \
            _Pragma("unroll")                                                 \
            for (int mt = 0; mt < 4; mt++) {                                  \
                int m0 = warp_m * 64 + mt * 16;                               \
                af[mt][0] = __float_as_uint(Ab[(m0 + g)     * AS_STRIDE + k1]); \
                af[mt][1] = __float_as_uint(Ab[(m0 + 8 + g) * AS_STRIDE + k1]); \
                af[mt][2] = __float_as_uint(Ab[(m0 + g)     * AS_STRIDE + k2]); \
                af[mt][3] = __float_as_uint(Ab[(m0 + 8 + g) * AS_STRIDE + k2]); \
            }                                                                 \
            _Pragma("unroll")                                                 \
            for (int nt = 0; nt < 4; nt++) {                                  \
                int n0 = warp_n * 32 + nt * 8;                                \
                bf[nt][0] = __float_as_uint(Bb[k1 * 128 + ((n0 + g) ^ (tig << 3))]); \
                bf[nt][1] = __float_as_uint(Bb[k2 * 128 + ((n0 + g) ^ (tig << 3))]); \
            }                                                                 \
            _Pragma("unroll")                                                 \
            for (int mt = 0; mt < 4; mt++)                                    \
                _Pragma("unroll")                                             \
                for (int nt = 0; nt < 4; nt++)                                \
                    MMA_TF32(acc[mt][nt], af[mt], bf[nt]);                    \
        }                                                                     \
    }

    LOADG(0);
    STORES(0);
    __syncthreads();
    for (int ks = 0; ks < 64; ks++) {
        const int cur = ks & 1;
        if (ks < 63) { LOADG(ks + 1); }
        COMPUTE(cur);
        if (ks < 63) { STORES(cur ^ 1); }
        __syncthreads();
    }

#pragma unroll
    for (int mt = 0; mt < 4; mt++) {
#pragma unroll
        for (int nt = 0; nt < 4; nt++) {
            int r  = row0 + warp_m * 64 + mt * 16 + g;
            int cc = col0 + warp_n * 32 + nt * 8 + tig * 2;
            *(float2*)(C + (size_t)r * C_DIM + cc) =
                make_float2(acc[mt][nt][0], acc[mt][nt][1]);
            *(float2*)(C + (size_t)(r + 8) * C_DIM + cc) =
                make_float2(acc[mt][nt][2], acc[mt][nt][3]);
        }
    }
#undef LOADG
#undef STORES
#undef COMPUTE
}

// ---------------- row squared norms ------------------------------------------
__global__ void rowsq_kernel(const float* __restrict__ xf, float* __restrict__ sq) {
    int row = blockIdx.x, tid = threadIdx.x;
    const float* x = xf + (size_t)row * C_DIM;
    float s = 0.f;
    for (int c = tid; c < C_DIM; c += 256) { float v = x[c]; s = fmaf(v, v, s); }
    for (int off = 16; off; off >>= 1) s += __shfl_xor_sync(0xffffffffu, s, off);
    __shared__ float r[8];
    if ((tid & 31) == 0) r[tid >> 5] = s;
    __syncthreads();
    if (tid == 0) { float t = 0.f; for (int w = 0; w < 8; w++) t += r[w]; sq[row] = t; }
}

// ---------------- pairwise distance: 128x64 tile, 8x4/thread -----------------
__global__ __launch_bounds__(256) void dist_kernel(
    const float* __restrict__ xf, const float* __restrict__ sq,
    float* __restrict__ D) {
    __shared__ float As[16][128];
    __shared__ float Bs[16][64];
    const int tid  = threadIdx.x;
    const int row0 = blockIdx.y * 128;
    const int col0 = blockIdx.x * 64;
    const int am = tid >> 2, ak = (tid & 3) << 2;
    const int ty = tid >> 4, tx = tid & 15;

    float4 a0, a1, b0;
    {
        a0 = *(const float4*)(xf + (size_t)(row0 + am)      * C_DIM + ak);
        a1 = *(const float4*)(xf + (size_t)(row0 + am + 64) * C_DIM + ak);
        b0 = *(const float4*)(xf + (size_t)(col0 + am)      * C_DIM + ak);
    }
    float acc[8][4] = {};

#define D_STORE()                                                             \
    {                                                                         \
        As[ak + 0][am] = a0.x; As[ak + 1][am] = a0.y;                         \
        As[ak + 2][am] = a0.z; As[ak + 3][am] = a0.w;                         \
        As[ak + 0][am + 64] = a1.x; As[ak + 1][am + 64] = a1.y;               \
        As[ak + 2][am + 64] = a1.z; As[ak + 3][am + 64] = a1.w;               \
        if (am < 64) {                                                        \
            Bs[ak + 0][am] = b0.x; Bs[ak + 1][am] = b0.y;                     \
            Bs[ak + 2][am] = b0.z; Bs[ak + 3][am] = b0.w;                     \
        }                                                                     \
    }
#define D_COMPUTE()                                                           \
    _Pragma("unroll")                                                         \
    for (int kt = 0; kt < 16; kt++) {                                         \
        float af[8], bf[4];                                                   \
        *(float4*)&af[0] = *(const float4*)&As[kt][ty * 8];                   \
        *(float4*)&af[4] = *(const float4*)&As[kt][ty * 8 + 4];               \
        *(float4*)&bf[0] = *(const float4*)&Bs[kt][tx * 4];                   \
        _Pragma("unroll")                                                     \
        for (int i = 0; i < 8; i++)                                           \
            _Pragma("unroll")                                                 \
            for (int j = 0; j < 4; j++)                                       \
                acc[i][j] = fmaf(af[i], bf[j], acc[i][j]);                    \
    }

    D_STORE();
    __syncthreads();
    for (int k0 = 16; k0 < C_DIM; k0 += 16) {
        a0 = *(const float4*)(xf + (size_t)(row0 + am)      * C_DIM + k0 + ak);
        a1 = *(const float4*)(xf + (size_t)(row0 + am + 64) * C_DIM + k0 + ak);
        b0 = *(const float4*)(xf + (size_t)(col0 + am)      * C_DIM + k0 + ak);
        D_COMPUTE();
        __syncthreads();
        D_STORE();
        __syncthreads();
    }
    D_COMPUTE();

#pragma unroll
    for (int i = 0; i < 8; i++) {
        int r = row0 + ty * 8 + i;
        float sqr = sq[r];
        float4 o;
        int c = col0 + tx * 4;
        o.x = sqrtf(fmaxf(sqr + sq[c + 0] - 2.f * acc[i][0], 0.f));
        o.y = sqrtf(fmaxf(sqr + sq[c + 1] - 2.f * acc[i][1], 0.f));
        o.z = sqrtf(fmaxf(sqr + sq[c + 2] - 2.f * acc[i][2], 0.f));
        o.w = sqrtf(fmaxf(sqr + sq[c + 3] - 2.f * acc[i][3], 0.f));
        *(float4*)(D + (size_t)r * N_NODES + c) = o;
    }
#undef D_STORE
#undef D_COMPUTE
}

// ---------------- kNN: 8 smallest per row (diag excluded), redux merge -------
__global__ void knn_kernel(const float* __restrict__ D, int* __restrict__ neigh) {
    int gw = (blockIdx.x * blockDim.x + threadIdx.x) >> 5;
    int lane = threadIdx.x & 31;
    if (gw >= N_NODES) return;
    const float* row = D + (size_t)gw * N_NODES;
    float val[8]; int idx[8];
#pragma unroll
    for (int r = 0; r < 8; r++) { val[r] = __int_as_float(0x7f800000); idx[r] = 0; }
    for (int j = lane; j < N_NODES; j += 32) {
        if (j == gw) continue;
        float v = row[j];
        if (v < val[7]) {
            val[7] = v; idx[7] = j;
#pragma unroll
            for (int p = 7; p > 0; p--) {
                if (val[p] < val[p - 1]) {
                    float tv = val[p]; val[p] = val[p - 1]; val[p - 1] = tv;
                    int   ti = idx[p]; idx[p] = idx[p - 1]; idx[p - 1] = ti;
                }
            }
        }
    }
    int ptr = 0;
#pragma unroll
    for (int r = 0; r < 8; r++) {
        unsigned vb = (ptr < 8) ? __float_as_uint(val[ptr]) : 0x7f800000u;
        unsigned vm = __reduce_min_sync(0xffffffffu, vb);
        unsigned mi = (ptr < 8 && vb == vm) ? (unsigned)idx[ptr] : 0x7fffffffu;
        unsigned im = __reduce_min_sync(0xffffffffu, mi);
        if (lane == 0) neigh[gw * KNB + r] = (int)im;
        if (ptr < 8 && vb == vm && (unsigned)idx[ptr] == im) ptr++;
    }
}

// ---------------- sequential k-means: 8 warps, 1 barrier/step ----------------
// thread t owns i = j*256 + t (j = 0..3). Every warp redundantly finalizes the
// previous centroid update and selects the cluster. Cross-step shared state is
// parity double-buffered (red, Drow_sh). D rows are prefetched with DEPTH 2:
// the row for step s+2 is issued at the top of step s into buf[s&1]; the rotate
// at the end of step s consumes buf[(s+1)&1] (issued a full step earlier), so
// L2 latency (~234-262 cyc) is fully off the per-step critical path.
__global__ __launch_bounds__(256) void kmeans_kernel(
    const float* __restrict__ D, const int* __restrict__ perm,
    int* __restrict__ assign_out) {
    __shared__ float S[KC * N_NODES];       // 32KB, owner-thread only
    __shared__ float Drow_sh[2][N_NODES];   // 8KB, parity double-buffered
    __shared__ int   sperm[N_NODES];        // 4KB, read-only after init
    __shared__ u64   red[2][8];             // parity double-buffered
    const int t = threadIdx.x;
    const int lane = t & 31;
    const int wid = t >> 5;
    const float INF = __int_as_float(0x7f800000);
    const unsigned FULL = 0xffffffffu;

    for (int i = t; i < N_NODES; i += 256) sperm[i] = perm[i];
    __syncthreads();
    int mycent = (lane < KC) ? sperm[lane] : 0;   // replicated in every warp
    for (int c = 0; c < KC; c++) {
        const float* row = D + (size_t)sperm[c] * N_NODES;
#pragma unroll
        for (int j = 0; j < 4; j++)
            S[c * N_NODES + j * 256 + t] = row[j * 256 + t];
    }
    // membership nibbles: slot j (global i = j*256+t), value = cluster+1
    unsigned nib = 0u;
    for (int c = 0; c < KC; c++) {
        int p = sperm[c];
        if ((p & 255) == t) nib |= (unsigned)(c + 1) << ((p >> 8) * 4);
    }
    // cur = row(step 0); buf[1] = row(step 1)  (consumed at step 0's rotate);
    // buf[0] gets row(step 2) at step 0.
    float cur[4], buf[2][4];
    {
        const float* r0 = D + (size_t)sperm[KC] * N_NODES;
        const float* r1 = D + (size_t)sperm[KC + 1] * N_NODES;
#pragma unroll
        for (int j = 0; j < 4; j++) {
            cur[j] = r0[j * 256 + t];
            Drow_sh[0][j * 256 + t] = cur[j];
            buf[1][j] = r1[j * 256 + t];
        }
    }
    int c_prev = -1;   // warp-uniform
    __syncthreads();

    for (int step = 0; step < NSTEPS; step++) {
        const int ni = sperm[KC + step];
        const int rb = step & 1;           // read buffer (Drow_sh + red write)
        const int wb = rb ^ 1;             // write buffer for next step's row
        // issue depth-2 prefetch FIRST (row for step+2 into buf[rb])
        {
            int nn = step + 2;
            if (nn >= NSTEPS) nn = NSTEPS - 1;
            const float* prow = D + (size_t)sperm[KC + nn] * N_NODES;
#pragma unroll
            for (int j = 0; j < 4; j++) buf[rb][j] = prow[j * 256 + t];
        }
        // finalize previous step's centroid (redundant in all 8 warps)
        if (step > 0) {
            u64 rv = (lane < 8) ? red[wb][lane] : ~0ull;   // prev step's buffer
            unsigned hv = (unsigned)(rv >> 32);
            unsigned hm = __reduce_min_sync(FULL, hv);
            unsigned cand = (hv == hm) ? (unsigned)(rv & 0xffffffffull) : 0xffffffffu;
            unsigned newc = __reduce_min_sync(FULL, cand);
            if (lane == c_prev) mycent = (int)newc;
        }
        // select nearest centroid for ni (redundant; first-index tiebreak)
        unsigned cb = (lane < KC) ? __float_as_uint(Drow_sh[rb][mycent]) : 0x7f800000u;
        unsigned cm = __reduce_min_sync(FULL, cb);
        unsigned cmask = __ballot_sync(FULL, cb == cm);
        const int c = __ffs(cmask) - 1;
        c_prev = c;
        const unsigned tgt = (unsigned)(c + 1);
        // S[c] += Drow; masked min (argmin of S over members == argmin of mean)
        float* Sc = S + c * N_NODES;
        float vv[4];
#pragma unroll
        for (int j = 0; j < 4; j++) {
            float s = Sc[j * 256 + t] + cur[j];
            Sc[j * 256 + t] = s;
            bool memb = (((nib >> (j * 4)) & 15u) == tgt) | ((j * 256 + t) == ni);
            vv[j] = memb ? s : INF;
        }
        float m0 = fminf(vv[0], vv[2]), m1 = fminf(vv[1], vv[3]);
        const float minv = fminf(m0, m1);
        unsigned msk = 0u;
#pragma unroll
        for (int j = 0; j < 4; j++) msk |= (vv[j] == minv) ? (1u << j) : 0u;
        const int besti = (__ffs(msk) - 1) * 256 + t;
        // per-warp argmin (value, then smallest global index)
        unsigned bb = __float_as_uint(minv);
        unsigned bm = __reduce_min_sync(FULL, bb);
        unsigned cand2 = (bb == bm) ? (unsigned)besti : 0xffffffffu;
        unsigned im = __reduce_min_sync(FULL, cand2);
        if (lane == 0) red[rb][wid] = ((u64)bm << 32) | im;
        // record assignment of ni
        if ((ni & 255) == t) nib |= tgt << ((ni >> 8) * 4);
        // rotate: next step's row (loaded one full step ago) into other buffer
#pragma unroll
        for (int j = 0; j < 4; j++) {
            float v = buf[wb][j];
            Drow_sh[wb][j * 256 + t] = v;
            cur[j] = v;
        }
        __syncthreads();   // red[rb] + Drow_sh[wb] visible for next step
    }
#pragma unroll
    for (int j = 0; j < 4; j++)
        assign_out[j * 256 + t] = (int)((nib >> (j * 4)) & 15u) - 1;
}

// ---------------- E[e] = sum_{v in neigh(e)} xf[v] ---------------------------
__global__ void agg_local_kernel(const float* __restrict__ xf, const int* __restrict__ neigh,
                                 float* __restrict__ E) {
    int e = blockIdx.x;
    int nb[KNB];
#pragma unroll
    for (int j = 0; j < KNB; j++) nb[j] = neigh[e * KNB + j];
    for (int c = threadIdx.x; c < C_DIM; c += 256) {
        float s = 0.f;
#pragma unroll
        for (int j = 0; j < KNB; j++) s += xf[(size_t)nb[j] * C_DIM + c];
        E[(size_t)e * C_DIM + c] = s;
    }
}

// ---------------- E[n+c] = sum_{assign[v]==c} xf[v] --------------------------
__global__ void agg_global_kernel(const float* __restrict__ xf, const int* __restrict__ assign_,
                                  float* __restrict__ E) {
    __shared__ int sa[N_NODES];
    int tid = threadIdx.x;
    for (int i = tid; i < N_NODES; i += 256) sa[i] = assign_[i];
    __syncthreads();
    int c = blockIdx.x;
    int col = blockIdx.y * 256 + tid;
    float s = 0.f;
    for (int i = 0; i < N_NODES; i++)
        if (sa[i] == c) s += xf[(size_t)i * C_DIM + col];
    E[(size_t)(N_NODES + c) * C_DIM + col] = s;
}

// ---------------- Y[v] = sum_{e: v in neigh(e)} X1[e] + X1[n+assign[v]] ------
__global__ void agg_out_kernel(const float* __restrict__ X1, const int* __restrict__ neigh,
                               const int* __restrict__ assign_, float* __restrict__ Y) {
    int v = blockIdx.x;
    __shared__ int list[N_NODES];
    __shared__ int cnt_s;
    int tid = threadIdx.x, lane = tid & 31, wid = tid >> 5;
    if (wid == 0) {
        int cnt = 0;
        for (int base = 0; base < N_NODES; base += 32) {
            int e = base + lane;
            const int4* p = (const int4*)(neigh + e * KNB);
            int4 q0 = p[0], q1 = p[1];
            bool m = (q0.x == v) | (q0.y == v) | (q0.z == v) | (q0.w == v) |
                     (q1.x == v) | (q1.y == v) | (q1.z == v) | (q1.w == v);
            unsigned msk = __ballot_sync(0xffffffffu, m);
            if (m) list[cnt + __popc(msk & ((1u << lane) - 1u))] = e;
            cnt += __popc(msk);
        }
        if (lane == 0) cnt_s = cnt;
    }
    __syncthreads();
    int cnt = cnt_s;
    int ge = N_NODES + assign_[v];
    float s[8];
#pragma unroll
    for (int w = 0; w < 8; w++) s[w] = X1[(size_t)ge * C_DIM + tid + w * 256];
    for (int t = 0; t < cnt; t++) {
        const float* xr = X1 + (size_t)list[t] * C_DIM;
#pragma unroll
        for (int w = 0; w < 8; w++) s[w] += xr[tid + w * 256];
    }
#pragma unroll
    for (int w = 0; w < 8; w++) Y[(size_t)v * C_DIM + tid + w * 256] = s[w];
}

// ---------------- host launcher ----------------------------------------------
extern "C" void kernel_launch(void* const* d_in, const int* in_sizes, int n_in,
                              void* d_out, int out_size) {
    const float* x0  = (const float*)d_in[0];
    const float* wfc = (const float*)d_in[1];
    const float* bfc = (const float*)d_in[2];
    const float* w1  = (const float*)d_in[3];
    const float* w2  = (const float*)d_in[4];
    float* out = (float*)d_out;

    float *xf, *sq, *D, *E, *X1, *Y;
    int *neigh, *perm, *assign_;
    cudaGetSymbolAddress((void**)&xf,      g_xf);
    cudaGetSymbolAddress((void**)&sq,      g_sq);
    cudaGetSymbolAddress((void**)&D,       g_D);
    cudaGetSymbolAddress((void**)&neigh,   g_neigh);
    cudaGetSymbolAddress((void**)&perm,    g_perm);
    cudaGetSymbolAddress((void**)&assign_, g_assign);
    cudaGetSymbolAddress((void**)&E,       g_E);
    cudaGetSymbolAddress((void**)&X1,      g_X1);
    cudaGetSymbolAddress((void**)&Y,       g_Y);

    const size_t dynsmem = (2 * AS_STAGE + 2 * BS_STAGE) * sizeof(float);  // 69632
    cudaFuncSetAttribute(mma_gemm_kernel,
                         cudaFuncAttributeMaxDynamicSharedMemorySize, (int)dynsmem);

    perm_kernel<<<1, 1024>>>(perm);
    sgemm_kernel<<<dim3(C_DIM / 128, N_NODES / 128), 256>>>(x0, wfc, bfc, xf,
                                                            N_NODES, C_DIM, C_DIM);
    rowsq_kernel<<<N_NODES, 256>>>(xf, sq);
    dist_kernel<<<dim3(N_NODES / 64, N_NODES / 128), 256>>>(xf, sq, D);
    knn_kernel<<<N_NODES / 8, 256>>>(D, neigh);
    kmeans_kernel<<<1, 256>>>(D, perm, assign_);
    agg_local_kernel<<<N_NODES, 256>>>(xf, neigh, E);
    agg_global_kernel<<<dim3(KC, C_DIM / 256), 256>>>(xf, assign_, E);
    mma_gemm_kernel<<<dim3(C_DIM / 128, E_PAD / 128), 256, dynsmem>>>(E, w1, X1);
    agg_out_kernel<<<N_NODES, 256>>>(X1, neigh, assign_, Y);
    mma_gemm_kernel<<<dim3(C_DIM / 128, N_NODES / 128), 256, dynsmem>>>(Y, w2, out);
}

// round 13
// speedup vs baseline: 1.0669x; 1.0084x over previous
#include <cuda_runtime.h>
#include <cstdint>
#include <cstddef>

#define N_NODES 1024
#define C_DIM   2048
#define KNB     8
#define KC      8
#define N_EDGES (N_NODES + KC)
#define NSTEPS  (N_NODES - KC)
#define E_PAD   1152   // padded edge-row count (9 * 128)

typedef unsigned long long u64;

// ---------------- scratch (static __device__, zero-initialized) --------------
__device__ float g_xf[N_NODES * C_DIM];
__device__ float g_sq[N_NODES];
__device__ float g_D[N_NODES * N_NODES];
__device__ int   g_neigh[N_NODES * KNB];
__device__ int   g_perm[N_NODES];
__device__ int   g_assign[N_NODES];
__device__ float g_E[E_PAD * C_DIM];    // rows 1032..1151 stay zero
__device__ float g_X1[E_PAD * C_DIM];
__device__ float g_Y[N_NODES * C_DIM];

// ---------------- helpers ----------------------------------------------------
__device__ __forceinline__ float to_tf32(float x) {
    uint32_t r;
    asm("cvt.rna.tf32.f32 %0, %1;" : "=r"(r) : "f"(x));
    return __uint_as_float(r);
}

#define MMA_TF32(d, a, b)                                                     \
    asm volatile(                                                             \
        "mma.sync.aligned.m16n8k8.row.col.f32.tf32.tf32.f32 "                 \
        "{%0,%1,%2,%3}, {%4,%5,%6,%7}, {%8,%9}, {%0,%1,%2,%3};"               \
        : "+f"((d)[0]), "+f"((d)[1]), "+f"((d)[2]), "+f"((d)[3])              \
        : "r"((a)[0]), "r"((a)[1]), "r"((a)[2]), "r"((a)[3]),                 \
          "r"((b)[0]), "r"((b)[1]))

// ---------------- threefry-2x32 (20 rounds) ----------------------------------
__device__ __forceinline__ void threefry2x32(unsigned k0, unsigned k1,
                                             unsigned& x0, unsigned& x1) {
    unsigned ks2 = k0 ^ k1 ^ 0x1BD11BDAu;
    x0 += k0; x1 += k1;
#define TF_R(r) { x0 += x1; x1 = (x1 << (r)) | (x1 >> (32 - (r))); x1 ^= x0; }
    TF_R(13) TF_R(15) TF_R(26) TF_R(6)
    x0 += k1;  x1 += ks2 + 1u;
    TF_R(17) TF_R(29) TF_R(16) TF_R(24)
    x0 += ks2; x1 += k0 + 2u;
    TF_R(13) TF_R(15) TF_R(26) TF_R(6)
    x0 += k0;  x1 += k1 + 3u;
    TF_R(17) TF_R(29) TF_R(16) TF_R(24)
    x0 += k1;  x1 += ks2 + 4u;
    TF_R(13) TF_R(15) TF_R(26) TF_R(6)
    x0 += ks2; x1 += k0 + 5u;
#undef TF_R
}

__global__ void perm_kernel(int* __restrict__ perm) {
    __shared__ u64 keys[N_NODES];
    int tid = threadIdx.x;
    unsigned s0, s1;
    { unsigned a0 = 0u, a1 = 1u; threefry2x32(0u, 42u, a0, a1); s0 = a0; s1 = a1; }
    if (tid < 512) {
        unsigned x0 = 0u, x1 = (unsigned)tid;
        threefry2x32(s0, s1, x0, x1);
        keys[tid] = ((u64)(x0 ^ x1) << 32) | (unsigned)tid;
        unsigned y0 = 0u, y1 = (unsigned)(tid + 512);
        threefry2x32(s0, s1, y0, y1);
        keys[tid + 512] = ((u64)(y0 ^ y1) << 32) | (unsigned)(tid + 512);
    }
    __syncthreads();
    for (int k = 2; k <= N_NODES; k <<= 1) {
        for (int j = k >> 1; j > 0; j >>= 1) {
            int ixj = tid ^ j;
            if (ixj > tid) {
                u64 a = keys[tid], b = keys[ixj];
                bool up = ((tid & k) == 0);
                if ((a > b) == up) { keys[tid] = b; keys[ixj] = a; }
            }
            __syncthreads();
        }
    }
    perm[tid] = (int)(keys[tid] & 0xffffffffull);
}

// ---------------- fp32 SGEMM (GEMM1 only): 128x128, 8x8/thread ---------------
__global__ __launch_bounds__(256) void sgemm_kernel(
    const float* __restrict__ A, const float* __restrict__ B,
    const float* __restrict__ bias, float* __restrict__ C,
    int M, int N, int K) {
    __shared__ float As[16][128];
    __shared__ float Bs[16][128];
    const int tid  = threadIdx.x;
    const int row0 = blockIdx.y * 128;
    const int col0 = blockIdx.x * 128;
    const int am = tid >> 2, ak = (tid & 3) << 2;
    const int bk = tid >> 5, bn = (tid & 31) << 2;
    const int ty = tid >> 4, tx = tid & 15;
    const float4 z4 = make_float4(0.f, 0.f, 0.f, 0.f);

    float4 a0, a1, b0, b1;
    {
        int r = row0 + am;
        a0 = (r      < M) ? *(const float4*)(A + (size_t)r        * K + ak) : z4;
        a1 = (r + 64 < M) ? *(const float4*)(A + (size_t)(r + 64) * K + ak) : z4;
        b0 = *(const float4*)(B + (size_t)bk       * N + col0 + bn);
        b1 = *(const float4*)(B + (size_t)(bk + 8) * N + col0 + bn);
    }
    float acc[8][8] = {};

#define STORE_TILES()                                                         \
    {                                                                         \
        As[ak + 0][am] = a0.x; As[ak + 1][am] = a0.y;                         \
        As[ak + 2][am] = a0.z; As[ak + 3][am] = a0.w;                         \
        As[ak + 0][am + 64] = a1.x; As[ak + 1][am + 64] = a1.y;               \
        As[ak + 2][am + 64] = a1.z; As[ak + 3][am + 64] = a1.w;               \
        *(float4*)&Bs[bk][bn]     = b0;                                       \
        *(float4*)&Bs[bk + 8][bn] = b1;                                       \
    }
#define COMPUTE_TILE()                                                        \
    _Pragma("unroll")                                                         \
    for (int kt = 0; kt < 16; kt++) {                                         \
        float af[8], bf[8];                                                   \
        *(float4*)&af[0] = *(const float4*)&As[kt][ty * 8];                   \
        *(float4*)&af[4] = *(const float4*)&As[kt][ty * 8 + 4];               \
        *(float4*)&bf[0] = *(const float4*)&Bs[kt][tx * 8];                   \
        *(float4*)&bf[4] = *(const float4*)&Bs[kt][tx * 8 + 4];               \
        _Pragma("unroll")                                                     \
        for (int i = 0; i < 8; i++)                                           \
            _Pragma("unroll")                                                 \
            for (int j = 0; j < 8; j++)                                       \
                acc[i][j] = fmaf(af[i], bf[j], acc[i][j]);                    \
    }

    STORE_TILES();
    __syncthreads();
    for (int k0 = 16; k0 < K; k0 += 16) {
        int r = row0 + am;
        a0 = (r      < M) ? *(const float4*)(A + (size_t)r        * K + k0 + ak) : z4;
        a1 = (r + 64 < M) ? *(const float4*)(A + (size_t)(r + 64) * K + k0 + ak) : z4;
        b0 = *(const float4*)(B + (size_t)(k0 + bk)     * N + col0 + bn);
        b1 = *(const float4*)(B + (size_t)(k0 + bk + 8) * N + col0 + bn);
        COMPUTE_TILE();
        __syncthreads();
        STORE_TILES();
        __syncthreads();
    }
    COMPUTE_TILE();

    float4 bias0 = z4, bias1 = z4;
    if (bias) {
        bias0 = *(const float4*)(bias + col0 + tx * 8);
        bias1 = *(const float4*)(bias + col0 + tx * 8 + 4);
    }
#pragma unroll
    for (int i = 0; i < 8; i++) {
        int r = row0 + ty * 8 + i;
        if (r < M) {
            float4 o0 = make_float4(acc[i][0] + bias0.x, acc[i][1] + bias0.y,
                                    acc[i][2] + bias0.z, acc[i][3] + bias0.w);
            float4 o1 = make_float4(acc[i][4] + bias1.x, acc[i][5] + bias1.y,
                                    acc[i][6] + bias1.z, acc[i][7] + bias1.w);
            *(float4*)(C + (size_t)r * N + col0 + tx * 8)     = o0;
            *(float4*)(C + (size_t)r * N + col0 + tx * 8 + 4) = o1;
        }
    }
#undef STORE_TILES
#undef COMPUTE_TILE
}

// ---------------- tf32 mma.sync GEMM: C[M,2048] = A[M,2048] @ B[2048,2048] ---
// kk-level software pipelining: fragments for kk+1 are loaded from smem while
// kk's mma chain issues (double-buffered frag registers) to break the serial
// LDS(29cyc) -> HMMA dependency per kk. Same mma order per accumulator.
#define AS_STRIDE 36
#define AS_STAGE  (128 * AS_STRIDE)
#define BS_STAGE  (32 * 128)

__global__ __launch_bounds__(256) void mma_gemm_kernel(
    const float* __restrict__ A, const float* __restrict__ B,
    float* __restrict__ C) {
    extern __shared__ float sm[];
    float* As = sm;                    // [2][128][36]
    float* Bs = sm + 2 * AS_STAGE;     // [2][32][128]
    const int tid  = threadIdx.x;
    const int lane = tid & 31, wid = tid >> 5;
    const int warp_m = wid >> 2, warp_n = wid & 3;
    const int g = lane >> 2, tig = lane & 3;
    const int row0 = blockIdx.y * 128, col0 = blockIdx.x * 128;

    float acc[4][4][4] = {};
    float4 ar[4], br[4];

#define LOADG(ks)                                                             \
    _Pragma("unroll")                                                         \
    for (int i = 0; i < 4; i++) {                                             \
        int ch = tid * 4 + i;                                                 \
        ar[i] = *(const float4*)(A + (size_t)(row0 + (ch >> 3)) * C_DIM       \
                                 + (ks) * 32 + (ch & 7) * 4);                 \
        br[i] = *(const float4*)(B + (size_t)((ks) * 32 + (ch >> 5)) * C_DIM  \
                                 + col0 + (ch & 31) * 4);                     \
    }

#define STORES(buf)                                                           \
    {                                                                         \
        float* Ab = As + (buf) * AS_STAGE;                                    \
        float* Bb = Bs + (buf) * BS_STAGE;                                    \
        _Pragma("unroll")                                                     \
        for (int i = 0; i < 4; i++) {                                         \
            int ch = tid * 4 + i;                                             \
            float4 v = ar[i];                                                 \
            v.x = to_tf32(v.x); v.y = to_tf32(v.y);                           \
            v.z = to_tf32(v.z); v.w = to_tf32(v.w);                           \
            *(float4*)(Ab + (ch >> 3) * AS_STRIDE + (ch & 7) * 4) = v;        \
            float4 w = br[i];                                                 \
            w.x = to_tf32(w.x); w.y = to_tf32(w.y);                           \
            w.z = to_tf32(w.z); w.w = to_tf32(w.w);                           \
            int kb = ch >> 5, n4 = ch & 31;                                   \
            *(float4*)(Bb + kb * 128 + ((n4 * 4) ^ ((kb & 3) << 3))) = w;     \
        }                                                                     \
    }

#define LOADFRAG(kk, s)                                                       \
    {                                                                         \
        const int k1 = (kk) * 8 + tig, k2 = (kk) * 8 + tig + 4;               \
        _Pragma("unroll")                                                     \
        for (int mt = 0; mt < 4; mt++) {                                      \
            int m0 = warp_m * 64 + mt * 16;                                   \
            af[s][mt][0] = __float_as_uint(Ab[(m0 + g)     * AS_STRIDE + k1]); \
            af[s][mt][1] = __float_as_uint(Ab[(m0 + 8 + g) * AS_STRIDE + k1]); \
            af[s][mt][2] = __float_as_uint(Ab[(m0 + g)     * AS_STRIDE + k2]); \
            af[s][mt][3] = __float_as_uint(Ab[(m0 + 8 + g) * AS_STRIDE + k2]); \
        }                                                                     \
        _Pragma("unroll")                                                     \
        for (int nt = 0; nt < 4; nt++) {                                      \
            int n0 = warp_n * 32 + nt * 8;                                    \
            bf[s][nt][0] = __float_as_uint(Bb[k1 * 128 + ((n0 + g) ^ (tig << 3))]); \
            bf[s][nt][1] = __float_as_uint(Bb[k2 * 128 + ((n0 + g) ^ (tig << 3))]); \
        }                                                                     \
    }

#define COMPUTE(buf)                                                          \
    {                                                                         \
        const float* Ab = As + (buf) * AS_STAGE;                              \
        const float* Bb = Bs + (buf) * BS_STAGE;                              \
        uint32_t af[2][4][4], bf[2][4][2];                                    \
        LOADFRAG(0, 0);                                                       \
        _Pragma("unroll")                                                     \
        for (int kk = 0; kk < 4; kk++) {                                      \
            if (kk < 3) LOADFRAG(kk + 1, (kk + 1) & 1);                       \
            const int s = kk & 1;                                             \
            _Pragma("unroll")                                                 \
            for (int mt = 0; mt < 4; mt++)                                    \
                _Pragma("unroll")                                             \
                for (int nt = 0; nt < 4; nt++)                                \
                    MMA_TF32(acc[mt][nt], af[s][mt], bf[s][nt]);              \
        }                                                                     \
    }

    LOADG(0);
    STORES(0);
    __syncthreads();
    for (int ks = 0; ks < 64; ks++) {
        const int cur = ks & 1;
        if (ks < 63) { LOADG(ks + 1); }
        COMPUTE(cur);
        if (ks < 63) { STORES(cur ^ 1); }
        __syncthreads();
    }

#pragma unroll
    for (int mt = 0; mt < 4; mt++) {
#pragma unroll
        for (int nt = 0; nt < 4; nt++) {
            int r  = row0 + warp_m * 64 + mt * 16 + g;
            int cc = col0 + warp_n * 32 + nt * 8 + tig * 2;
            *(float2*)(C + (size_t)r * C_DIM + cc) =
                make_float2(acc[mt][nt][0], acc[mt][nt][1]);
            *(float2*)(C + (size_t)(r + 8) * C_DIM + cc) =
                make_float2(acc[mt][nt][2], acc[mt][nt][3]);
        }
    }
#undef LOADG
#undef STORES
#undef LOADFRAG
#undef COMPUTE
}

// ---------------- row squared norms ------------------------------------------
__global__ void rowsq_kernel(const float* __restrict__ xf, float* __restrict__ sq) {
    int row = blockIdx.x, tid = threadIdx.x;
    const float* x = xf + (size_t)row * C_DIM;
    float s = 0.f;
    for (int c = tid; c < C_DIM; c += 256) { float v = x[c]; s = fmaf(v, v, s); }
    for (int off = 16; off; off >>= 1) s += __shfl_xor_sync(0xffffffffu, s, off);
    __shared__ float r[8];
    if ((tid & 31) == 0) r[tid >> 5] = s;
    __syncthreads();
    if (tid == 0) { float t = 0.f; for (int w = 0; w < 8; w++) t += r[w]; sq[row] = t; }
}

// ---------------- pairwise distance: symmetric pair tiles 64x64 ---------------
// CTA computes tile (bi, bj) with bi <= bj (136 CTAs = 1 wave) and writes both
// D[r][c] and its mirror D[c][r] (values bit-identical: same fma chain, a+b
// commutative). 128 threads, 8x4 accumulators per thread.
__global__ __launch_bounds__(128) void dist_kernel(
    const float* __restrict__ xf, const float* __restrict__ sq,
    float* __restrict__ D) {
    __shared__ float As[16][64];
    __shared__ float Bs[16][64];
    int bb = blockIdx.x, bi = 0;
    while (bb >= 16 - bi) { bb -= 16 - bi; bi++; }
    const int bj = bi + bb;
    const int r0 = bi * 64, c0 = bj * 64;
    const int tid = threadIdx.x;
    const int am = tid & 63;          // row within tile (conflict-free stores)
    const int ak = (tid >> 6) << 3;   // k-offset: 0 or 8
    const int ty = tid >> 4, tx = tid & 15;

    float4 a0, a1, b0, b1;
    a0 = *(const float4*)(xf + (size_t)(r0 + am) * C_DIM + ak);
    a1 = *(const float4*)(xf + (size_t)(r0 + am) * C_DIM + ak + 4);
    b0 = *(const float4*)(xf + (size_t)(c0 + am) * C_DIM + ak);
    b1 = *(const float4*)(xf + (size_t)(c0 + am) * C_DIM + ak + 4);
    float acc[8][4] = {};

#define DS_STORE()                                                            \
    {                                                                         \
        As[ak + 0][am] = a0.x; As[ak + 1][am] = a0.y;                         \
        As[ak + 2][am] = a0.z; As[ak + 3][am] = a0.w;                         \
        As[ak + 4][am] = a1.x; As[ak + 5][am] = a1.y;                         \
        As[ak + 6][am] = a1.z; As[ak + 7][am] = a1.w;                         \
        Bs[ak + 0][am] = b0.x; Bs[ak + 1][am] = b0.y;                         \
        Bs[ak + 2][am] = b0.z; Bs[ak + 3][am] = b0.w;                         \
        Bs[ak + 4][am] = b1.x; Bs[ak + 5][am] = b1.y;                         \
        Bs[ak + 6][am] = b1.z; Bs[ak + 7][am] = b1.w;                         \
    }
#define DS_COMPUTE()                                                          \
    _Pragma("unroll")                                                         \
    for (int kt = 0; kt < 16; kt++) {                                         \
        float af[8], bf[4];                                                   \
        *(float4*)&af[0] = *(const float4*)&As[kt][ty * 8];                   \
        *(float4*)&af[4] = *(const float4*)&As[kt][ty * 8 + 4];               \
        *(float4*)&bf[0] = *(const float4*)&Bs[kt][tx * 4];                   \
        _Pragma("unroll")                                                     \
        for (int i = 0; i < 8; i++)                                           \
            _Pragma("unroll")                                                 \
            for (int j = 0; j < 4; j++)                                       \
                acc[i][j] = fmaf(af[i], bf[j], acc[i][j]);                    \
    }

    DS_STORE();
    __syncthreads();
    for (int k0 = 16; k0 < C_DIM; k0 += 16) {
        a0 = *(const float4*)(xf + (size_t)(r0 + am) * C_DIM + k0 + ak);
        a1 = *(const float4*)(xf + (size_t)(r0 + am) * C_DIM + k0 + ak + 4);
        b0 = *(const float4*)(xf + (size_t)(c0 + am) * C_DIM + k0 + ak);
        b1 = *(const float4*)(xf + (size_t)(c0 + am) * C_DIM + k0 + ak + 4);
        DS_COMPUTE();
        __syncthreads();
        DS_STORE();
        __syncthreads();
    }
    DS_COMPUTE();

#pragma unroll
    for (int i = 0; i < 8; i++) {
        int r = r0 + ty * 8 + i;
        float sqr = sq[r];
        float4 o;
        int c = c0 + tx * 4;
        o.x = sqrtf(fmaxf(sqr + sq[c + 0] - 2.f * acc[i][0], 0.f));
        o.y = sqrtf(fmaxf(sqr + sq[c + 1] - 2.f * acc[i][1], 0.f));
        o.z = sqrtf(fmaxf(sqr + sq[c + 2] - 2.f * acc[i][2], 0.f));
        o.w = sqrtf(fmaxf(sqr + sq[c + 3] - 2.f * acc[i][3], 0.f));
        *(float4*)(D + (size_t)r * N_NODES + c) = o;
        if (bi != bj) {
            D[(size_t)(c + 0) * N_NODES + r] = o.x;
            D[(size_t)(c + 1) * N_NODES + r] = o.y;
            D[(size_t)(c + 2) * N_NODES + r] = o.z;
            D[(size_t)(c + 3) * N_NODES + r] = o.w;
        }
    }
#undef DS_STORE
#undef DS_COMPUTE
}

// ---------------- kNN: 8 smallest per row (diag excluded), redux merge -------
__global__ void knn_kernel(const float* __restrict__ D, int* __restrict__ neigh) {
    int gw = (blockIdx.x * blockDim.x + threadIdx.x) >> 5;
    int lane = threadIdx.x & 31;
    if (gw >= N_NODES) return;
    const float* row = D + (size_t)gw * N_NODES;
    float val[8]; int idx[8];
#pragma unroll
    for (int r = 0; r < 8; r++) { val[r] = __int_as_float(0x7f800000); idx[r] = 0; }
    for (int j = lane; j < N_NODES; j += 32) {
        if (j == gw) continue;
        float v = row[j];
        if (v < val[7]) {
            val[7] = v; idx[7] = j;
#pragma unroll
            for (int p = 7; p > 0; p--) {
                if (val[p] < val[p - 1]) {
                    float tv = val[p]; val[p] = val[p - 1]; val[p - 1] = tv;
                    int   ti = idx[p]; idx[p] = idx[p - 1]; idx[p - 1] = ti;
                }
            }
        }
    }
    int ptr = 0;
#pragma unroll
    for (int r = 0; r < 8; r++) {
        unsigned vb = (ptr < 8) ? __float_as_uint(val[ptr]) : 0x7f800000u;
        unsigned vm = __reduce_min_sync(0xffffffffu, vb);
        unsigned mi = (ptr < 8 && vb == vm) ? (unsigned)idx[ptr] : 0x7fffffffu;
        unsigned im = __reduce_min_sync(0xffffffffu, mi);
        if (lane == 0) neigh[gw * KNB + r] = (int)im;
        if (ptr < 8 && vb == vm && (unsigned)idx[ptr] == im) ptr++;
    }
}

// ---------------- sequential k-means: 8 warps, 1 barrier/step ----------------
// (unchanged from R12: parity double-buffered red/Drow_sh, depth-2 prefetch)
__global__ __launch_bounds__(256) void kmeans_kernel(
    const float* __restrict__ D, const int* __restrict__ perm,
    int* __restrict__ assign_out) {
    __shared__ float S[KC * N_NODES];       // 32KB, owner-thread only
    __shared__ float Drow_sh[2][N_NODES];   // 8KB, parity double-buffered
    __shared__ int   sperm[N_NODES];        // 4KB, read-only after init
    __shared__ u64   red[2][8];             // parity double-buffered
    const int t = threadIdx.x;
    const int lane = t & 31;
    const int wid = t >> 5;
    const float INF = __int_as_float(0x7f800000);
    const unsigned FULL = 0xffffffffu;

    for (int i = t; i < N_NODES; i += 256) sperm[i] = perm[i];
    __syncthreads();
    int mycent = (lane < KC) ? sperm[lane] : 0;   // replicated in every warp
    for (int c = 0; c < KC; c++) {
        const float* row = D + (size_t)sperm[c] * N_NODES;
#pragma unroll
        for (int j = 0; j < 4; j++)
            S[c * N_NODES + j * 256 + t] = row[j * 256 + t];
    }
    unsigned nib = 0u;
    for (int c = 0; c < KC; c++) {
        int p = sperm[c];
        if ((p & 255) == t) nib |= (unsigned)(c + 1) << ((p >> 8) * 4);
    }
    float cur[4], buf[2][4];
    {
        const float* r0 = D + (size_t)sperm[KC] * N_NODES;
        const float* r1 = D + (size_t)sperm[KC + 1] * N_NODES;
#pragma unroll
        for (int j = 0; j < 4; j++) {
            cur[j] = r0[j * 256 + t];
            Drow_sh[0][j * 256 + t] = cur[j];
            buf[1][j] = r1[j * 256 + t];
        }
    }
    int c_prev = -1;   // warp-uniform
    __syncthreads();

    for (int step = 0; step < NSTEPS; step++) {
        const int ni = sperm[KC + step];
        const int rb = step & 1;
        const int wb = rb ^ 1;
        // depth-2 prefetch (row for step+2 into buf[rb])
        {
            int nn = step + 2;
            if (nn >= NSTEPS) nn = NSTEPS - 1;
            const float* prow = D + (size_t)sperm[KC + nn] * N_NODES;
#pragma unroll
            for (int j = 0; j < 4; j++) buf[rb][j] = prow[j * 256 + t];
        }
        // finalize previous step's centroid (redundant in all 8 warps)
        if (step > 0) {
            u64 rv = (lane < 8) ? red[wb][lane] : ~0ull;
            unsigned hv = (unsigned)(rv >> 32);
            unsigned hm = __reduce_min_sync(FULL, hv);
            unsigned cand = (hv == hm) ? (unsigned)(rv & 0xffffffffull) : 0xffffffffu;
            unsigned newc = __reduce_min_sync(FULL, cand);
            if (lane == c_prev) mycent = (int)newc;
        }
        // select nearest centroid for ni (redundant; first-index tiebreak)
        unsigned cb = (lane < KC) ? __float_as_uint(Drow_sh[rb][mycent]) : 0x7f800000u;
        unsigned cm = __reduce_min_sync(FULL, cb);
        unsigned cmask = __ballot_sync(FULL, cb == cm);
        const int c = __ffs(cmask) - 1;
        c_prev = c;
        const unsigned tgt = (unsigned)(c + 1);
        // S[c] += Drow; masked min (argmin of S over members == argmin of mean)
        float* Sc = S + c * N_NODES;
        float vv[4];
#pragma unroll
        for (int j = 0; j < 4; j++) {
            float s = Sc[j * 256 + t] + cur[j];
            Sc[j * 256 + t] = s;
            bool memb = (((nib >> (j * 4)) & 15u) == tgt) | ((j * 256 + t) == ni);
            vv[j] = memb ? s : INF;
        }
        float m0 = fminf(vv[0], vv[2]), m1 = fminf(vv[1], vv[3]);
        const float minv = fminf(m0, m1);
        unsigned msk = 0u;
#pragma unroll
        for (int j = 0; j < 4; j++) msk |= (vv[j] == minv) ? (1u << j) : 0u;
        const int besti = (__ffs(msk) - 1) * 256 + t;
        unsigned bb = __float_as_uint(minv);
        unsigned bm = __reduce_min_sync(FULL, bb);
        unsigned cand2 = (bb == bm) ? (unsigned)besti : 0xffffffffu;
        unsigned im = __reduce_min_sync(FULL, cand2);
        if (lane == 0) red[rb][wid] = ((u64)bm << 32) | im;
        if ((ni & 255) == t) nib |= tgt << ((ni >> 8) * 4);
#pragma unroll
        for (int j = 0; j < 4; j++) {
            float v = buf[wb][j];
            Drow_sh[wb][j * 256 + t] = v;
            cur[j] = v;
        }
        __syncthreads();
    }
#pragma unroll
    for (int j = 0; j < 4; j++)
        assign_out[j * 256 + t] = (int)((nib >> (j * 4)) & 15u) - 1;
}

// ---------------- E[e] = sum_{v in neigh(e)} xf[v] ---------------------------
__global__ void agg_local_kernel(const float* __restrict__ xf, const int* __restrict__ neigh,
                                 float* __restrict__ E) {
    int e = blockIdx.x;
    int nb[KNB];
#pragma unroll
    for (int j = 0; j < KNB; j++) nb[j] = neigh[e * KNB + j];
    for (int c = threadIdx.x; c < C_DIM; c += 256) {
        float s = 0.f;
#pragma unroll
        for (int j = 0; j < KNB; j++) s += xf[(size_t)nb[j] * C_DIM + c];
        E[(size_t)e * C_DIM + c] = s;
    }
}

// ---------------- E[n+c] = sum_{assign[v]==c} xf[v] --------------------------
__global__ void agg_global_kernel(const float* __restrict__ xf, const int* __restrict__ assign_,
                                  float* __restrict__ E) {
    __shared__ int sa[N_NODES];
    int tid = threadIdx.x;
    for (int i = tid; i < N_NODES; i += 256) sa[i] = assign_[i];
    __syncthreads();
    int c = blockIdx.x;
    int col = blockIdx.y * 256 + tid;
    float s = 0.f;
    for (int i = 0; i < N_NODES; i++)
        if (sa[i] == c) s += xf[(size_t)i * C_DIM + col];
    E[(size_t)(N_NODES + c) * C_DIM + col] = s;
}

// ---------------- Y[v] = sum_{e: v in neigh(e)} X1[e] + X1[n+assign[v]] ------
__global__ void agg_out_kernel(const float* __restrict__ X1, const int* __restrict__ neigh,
                               const int* __restrict__ assign_, float* __restrict__ Y) {
    int v = blockIdx.x;
    __shared__ int list[N_NODES];
    __shared__ int cnt_s;
    int tid = threadIdx.x, lane = tid & 31, wid = tid >> 5;
    if (wid == 0) {
        int cnt = 0;
        for (int base = 0; base < N_NODES; base += 32) {
            int e = base + lane;
            const int4* p = (const int4*)(neigh + e * KNB);
            int4 q0 = p[0], q1 = p[1];
            bool m = (q0.x == v) | (q0.y == v) | (q0.z == v) | (q0.w == v) |
                     (q1.x == v) | (q1.y == v) | (q1.z == v) | (q1.w == v);
            unsigned msk = __ballot_sync(0xffffffffu, m);
            if (m) list[cnt + __popc(msk & ((1u << lane) - 1u))] = e;
            cnt += __popc(msk);
        }
        if (lane == 0) cnt_s = cnt;
    }
    __syncthreads();
    int cnt = cnt_s;
    int ge = N_NODES + assign_[v];
    float s[8];
#pragma unroll
    for (int w = 0; w < 8; w++) s[w] = X1[(size_t)ge * C_DIM + tid + w * 256];
    for (int t = 0; t < cnt; t++) {
        const float* xr = X1 + (size_t)list[t] * C_DIM;
#pragma unroll
        for (int w = 0; w < 8; w++) s[w] += xr[tid + w * 256];
    }
#pragma unroll
    for (int w = 0; w < 8; w++) Y[(size_t)v * C_DIM + tid + w * 256] = s[w];
}

// ---------------- host launcher ----------------------------------------------
extern "C" void kernel_launch(void* const* d_in, const int* in_sizes, int n_in,
                              void* d_out, int out_size) {
    const float* x0  = (const float*)d_in[0];
    const float* wfc = (const float*)d_in[1];
    const float* bfc = (const float*)d_in[2];
    const float* w1  = (const float*)d_in[3];
    const float* w2  = (const float*)d_in[4];
    float* out = (float*)d_out;

    float *xf, *sq, *D, *E, *X1, *Y;
    int *neigh, *perm, *assign_;
    cudaGetSymbolAddress((void**)&xf,      g_xf);
    cudaGetSymbolAddress((void**)&sq,      g_sq);
    cudaGetSymbolAddress((void**)&D,       g_D);
    cudaGetSymbolAddress((void**)&neigh,   g_neigh);
    cudaGetSymbolAddress((void**)&perm,    g_perm);
    cudaGetSymbolAddress((void**)&assign_, g_assign);
    cudaGetSymbolAddress((void**)&E,       g_E);
    cudaGetSymbolAddress((void**)&X1,      g_X1);
    cudaGetSymbolAddress((void**)&Y,       g_Y);

    const size_t dynsmem = (2 * AS_STAGE + 2 * BS_STAGE) * sizeof(float);  // 69632
    cudaFuncSetAttribute(mma_gemm_kernel,
                         cudaFuncAttributeMaxDynamicSharedMemorySize, (int)dynsmem);

    perm_kernel<<<1, 1024>>>(perm);
    sgemm_kernel<<<dim3(C_DIM / 128, N_NODES / 128), 256>>>(x0, wfc, bfc, xf,
                                                            N_NODES, C_DIM, C_DIM);
    rowsq_kernel<<<N_NODES, 256>>>(xf, sq);
    dist_kernel<<<136, 128>>>(xf, sq, D);
    knn_kernel<<<N_NODES / 8, 256>>>(D, neigh);
    kmeans_kernel<<<1, 256>>>(D, perm, assign_);
    agg_local_kernel<<<N_NODES, 256>>>(xf, neigh, E);
    agg_global_kernel<<<dim3(KC, C_DIM / 256), 256>>>(xf, assign_, E);
    mma_gemm_kernel<<<dim3(C_DIM / 128, E_PAD / 128), 256, dynsmem>>>(E, w1, X1);
    agg_out_kernel<<<N_NODES, 256>>>(X1, neigh, assign_, Y);
    mma_gemm_kernel<<<dim3(C_DIM / 128, N_NODES / 128), 256, dynsmem>>>(Y, w2, out);
}

// round 14
// speedup vs baseline: 1.0994x; 1.0305x over previous
#include <cuda_runtime.h>
#include <cstdint>
#include <cstddef>

#define N_NODES 1024
#define C_DIM   2048
#define KNB     8
#define KC      8
#define N_EDGES (N_NODES + KC)
#define NSTEPS  (N_NODES - KC)
#define E_PAD   1152   // padded edge-row count (9 * 128)

typedef unsigned long long u64;

// ---------------- scratch (static __device__, zero-initialized) --------------
__device__ float g_xf[N_NODES * C_DIM];
__device__ float g_sq[N_NODES];
__device__ float g_D[N_NODES * N_NODES];
__device__ int   g_neigh[N_NODES * KNB];
__device__ int   g_perm[N_NODES];
__device__ int   g_assign[N_NODES];
__device__ float g_E[E_PAD * C_DIM];    // rows 1032..1151 stay zero
__device__ float g_X1[E_PAD * C_DIM];
__device__ float g_Y[N_NODES * C_DIM];

// ---------------- helpers ----------------------------------------------------
__device__ __forceinline__ float to_tf32(float x) {
    uint32_t r;
    asm("cvt.rna.tf32.f32 %0, %1;" : "=r"(r) : "f"(x));
    return __uint_as_float(r);
}

#define MMA_TF32(d, a, b)                                                     \
    asm volatile(                                                             \
        "mma.sync.aligned.m16n8k8.row.col.f32.tf32.tf32.f32 "                 \
        "{%0,%1,%2,%3}, {%4,%5,%6,%7}, {%8,%9}, {%0,%1,%2,%3};"               \
        : "+f"((d)[0]), "+f"((d)[1]), "+f"((d)[2]), "+f"((d)[3])              \
        : "r"((a)[0]), "r"((a)[1]), "r"((a)[2]), "r"((a)[3]),                 \
          "r"((b)[0]), "r"((b)[1]))

// ---------------- threefry-2x32 (20 rounds) ----------------------------------
__device__ __forceinline__ void threefry2x32(unsigned k0, unsigned k1,
                                             unsigned& x0, unsigned& x1) {
    unsigned ks2 = k0 ^ k1 ^ 0x1BD11BDAu;
    x0 += k0; x1 += k1;
#define TF_R(r) { x0 += x1; x1 = (x1 << (r)) | (x1 >> (32 - (r))); x1 ^= x0; }
    TF_R(13) TF_R(15) TF_R(26) TF_R(6)
    x0 += k1;  x1 += ks2 + 1u;
    TF_R(17) TF_R(29) TF_R(16) TF_R(24)
    x0 += ks2; x1 += k0 + 2u;
    TF_R(13) TF_R(15) TF_R(26) TF_R(6)
    x0 += k0;  x1 += k1 + 3u;
    TF_R(17) TF_R(29) TF_R(16) TF_R(24)
    x0 += k1;  x1 += ks2 + 4u;
    TF_R(13) TF_R(15) TF_R(26) TF_R(6)
    x0 += ks2; x1 += k0 + 5u;
#undef TF_R
}

__global__ void perm_kernel(int* __restrict__ perm) {
    __shared__ u64 keys[N_NODES];
    int tid = threadIdx.x;
    unsigned s0, s1;
    { unsigned a0 = 0u, a1 = 1u; threefry2x32(0u, 42u, a0, a1); s0 = a0; s1 = a1; }
    if (tid < 512) {
        unsigned x0 = 0u, x1 = (unsigned)tid;
        threefry2x32(s0, s1, x0, x1);
        keys[tid] = ((u64)(x0 ^ x1) << 32) | (unsigned)tid;
        unsigned y0 = 0u, y1 = (unsigned)(tid + 512);
        threefry2x32(s0, s1, y0, y1);
        keys[tid + 512] = ((u64)(y0 ^ y1) << 32) | (unsigned)(tid + 512);
    }
    __syncthreads();
    for (int k = 2; k <= N_NODES; k <<= 1) {
        for (int j = k >> 1; j > 0; j >>= 1) {
            int ixj = tid ^ j;
            if (ixj > tid) {
                u64 a = keys[tid], b = keys[ixj];
                bool up = ((tid & k) == 0);
                if ((a > b) == up) { keys[tid] = b; keys[ixj] = a; }
            }
            __syncthreads();
        }
    }
    perm[tid] = (int)(keys[tid] & 0xffffffffull);
}

// ---------------- fp32 SGEMM (GEMM1 only): 128x128, 8x8/thread ---------------
__global__ __launch_bounds__(256) void sgemm_kernel(
    const float* __restrict__ A, const float* __restrict__ B,
    const float* __restrict__ bias, float* __restrict__ C,
    int M, int N, int K) {
    __shared__ float As[16][128];
    __shared__ float Bs[16][128];
    const int tid  = threadIdx.x;
    const int row0 = blockIdx.y * 128;
    const int col0 = blockIdx.x * 128;
    const int am = tid >> 2, ak = (tid & 3) << 2;
    const int bk = tid >> 5, bn = (tid & 31) << 2;
    const int ty = tid >> 4, tx = tid & 15;
    const float4 z4 = make_float4(0.f, 0.f, 0.f, 0.f);

    float4 a0, a1, b0, b1;
    {
        int r = row0 + am;
        a0 = (r      < M) ? *(const float4*)(A + (size_t)r        * K + ak) : z4;
        a1 = (r + 64 < M) ? *(const float4*)(A + (size_t)(r + 64) * K + ak) : z4;
        b0 = *(const float4*)(B + (size_t)bk       * N + col0 + bn);
        b1 = *(const float4*)(B + (size_t)(bk + 8) * N + col0 + bn);
    }
    float acc[8][8] = {};

#define STORE_TILES()                                                         \
    {                                                                         \
        As[ak + 0][am] = a0.x; As[ak + 1][am] = a0.y;                         \
        As[ak + 2][am] = a0.z; As[ak + 3][am] = a0.w;                         \
        As[ak + 0][am + 64] = a1.x; As[ak + 1][am + 64] = a1.y;               \
        As[ak + 2][am + 64] = a1.z; As[ak + 3][am + 64] = a1.w;               \
        *(float4*)&Bs[bk][bn]     = b0;                                       \
        *(float4*)&Bs[bk + 8][bn] = b1;                                       \
    }
#define COMPUTE_TILE()                                                        \
    _Pragma("unroll")                                                         \
    for (int kt = 0; kt < 16; kt++) {                                         \
        float af[8], bf[8];                                                   \
        *(float4*)&af[0] = *(const float4*)&As[kt][ty * 8];                   \
        *(float4*)&af[4] = *(const float4*)&As[kt][ty * 8 + 4];               \
        *(float4*)&bf[0] = *(const float4*)&Bs[kt][tx * 8];                   \
        *(float4*)&bf[4] = *(const float4*)&Bs[kt][tx * 8 + 4];               \
        _Pragma("unroll")                                                     \
        for (int i = 0; i < 8; i++)                                           \
            _Pragma("unroll")                                                 \
            for (int j = 0; j < 8; j++)                                       \
                acc[i][j] = fmaf(af[i], bf[j], acc[i][j]);                    \
    }

    STORE_TILES();
    __syncthreads();
    for (int k0 = 16; k0 < K; k0 += 16) {
        int r = row0 + am;
        a0 = (r      < M) ? *(const float4*)(A + (size_t)r        * K + k0 + ak) : z4;
        a1 = (r + 64 < M) ? *(const float4*)(A + (size_t)(r + 64) * K + k0 + ak) : z4;
        b0 = *(const float4*)(B + (size_t)(k0 + bk)     * N + col0 + bn);
        b1 = *(const float4*)(B + (size_t)(k0 + bk + 8) * N + col0 + bn);
        COMPUTE_TILE();
        __syncthreads();
        STORE_TILES();
        __syncthreads();
    }
    COMPUTE_TILE();

    float4 bias0 = z4, bias1 = z4;
    if (bias) {
        bias0 = *(const float4*)(bias + col0 + tx * 8);
        bias1 = *(const float4*)(bias + col0 + tx * 8 + 4);
    }
#pragma unroll
    for (int i = 0; i < 8; i++) {
        int r = row0 + ty * 8 + i;
        if (r < M) {
            float4 o0 = make_float4(acc[i][0] + bias0.x, acc[i][1] + bias0.y,
                                    acc[i][2] + bias0.z, acc[i][3] + bias0.w);
            float4 o1 = make_float4(acc[i][4] + bias1.x, acc[i][5] + bias1.y,
                                    acc[i][6] + bias1.z, acc[i][7] + bias1.w);
            *(float4*)(C + (size_t)r * N + col0 + tx * 8)     = o0;
            *(float4*)(C + (size_t)r * N + col0 + tx * 8 + 4) = o1;
        }
    }
#undef STORE_TILES
#undef COMPUTE_TILE
}

// ---------------- tf32 mma.sync GEMM: C[M,2048] = A[M,2048] @ B[2048,2048] ---
#define AS_STRIDE 36
#define AS_STAGE  (128 * AS_STRIDE)
#define BS_STAGE  (32 * 128)

__global__ __launch_bounds__(256) void mma_gemm_kernel(
    const float* __restrict__ A, const float* __restrict__ B,
    float* __restrict__ C) {
    extern __shared__ float sm[];
    float* As = sm;                    // [2][128][36]
    float* Bs = sm + 2 * AS_STAGE;     // [2][32][128]
    const int tid  = threadIdx.x;
    const int lane = tid & 31, wid = tid >> 5;
    const int warp_m = wid >> 2, warp_n = wid & 3;
    const int g = lane >> 2, tig = lane & 3;
    const int row0 = blockIdx.y * 128, col0 = blockIdx.x * 128;

    float acc[4][4][4] = {};
    float4 ar[4], br[4];

#define LOADG(ks)                                                             \
    _Pragma("unroll")                                                         \
    for (int i = 0; i < 4; i++) {                                             \
        int ch = tid * 4 + i;                                                 \
        ar[i] = *(const float4*)(A + (size_t)(row0 + (ch >> 3)) * C_DIM       \
                                 + (ks) * 32 + (ch & 7) * 4);                 \
        br[i] = *(const float4*)(B + (size_t)((ks) * 32 + (ch >> 5)) * C_DIM  \
                                 + col0 + (ch & 31) * 4);                     \
    }

#define STORES(buf)                                                           \
    {                                                                         \
        float* Ab = As + (buf) * AS_STAGE;                                    \
        float* Bb = Bs + (buf) * BS_STAGE;                                    \
        _Pragma("unroll")                                                     \
        for (int i = 0; i < 4; i++) {                                         \
            int ch = tid * 4 + i;                                             \
            float4 v = ar[i];                                                 \
            v.x = to_tf32(v.x); v.y = to_tf32(v.y);                           \
            v.z = to_tf32(v.z); v.w = to_tf32(v.w);                           \
            *(float4*)(Ab + (ch >> 3) * AS_STRIDE + (ch & 7) * 4) = v;        \
            float4 w = br[i];                                                 \
            w.x = to_tf32(w.x); w.y = to_tf32(w.y);                           \
            w.z = to_tf32(w.z); w.w = to_tf32(w.w);                           \
            int kb = ch >> 5, n4 = ch & 31;                                   \
            *(float4*)(Bb + kb * 128 + ((n4 * 4) ^ ((kb & 3) << 3))) = w;     \
        }                                                                     \
    }

#define LOADFRAG(kk, s)                                                       \
    {                                                                         \
        const int k1 = (kk) * 8 + tig, k2 = (kk) * 8 + tig + 4;               \
        _Pragma("unroll")                                                     \
        for (int mt = 0; mt < 4; mt++) {                                      \
            int m0 = warp_m * 64 + mt * 16;                                   \
            af[s][mt][0] = __float_as_uint(Ab[(m0 + g)     * AS_STRIDE + k1]); \
            af[s][mt][1] = __float_as_uint(Ab[(m0 + 8 + g) * AS_STRIDE + k1]); \
            af[s][mt][2] = __float_as_uint(Ab[(m0 + g)     * AS_STRIDE + k2]); \
            af[s][mt][3] = __float_as_uint(Ab[(m0 + 8 + g) * AS_STRIDE + k2]); \
        }                                                                     \
        _Pragma("unroll")                                                     \
        for (int nt = 0; nt < 4; nt++) {                                      \
            int n0 = warp_n * 32 + nt * 8;                                    \
            bf[s][nt][0] = __float_as_uint(Bb[k1 * 128 + ((n0 + g) ^ (tig << 3))]); \
            bf[s][nt][1] = __float_as_uint(Bb[k2 * 128 + ((n0 + g) ^ (tig << 3))]); \
        }                                                                     \
    }

#define COMPUTE(buf)                                                          \
    {                                                                         \
        const float* Ab = As + (buf) * AS_STAGE;                              \
        const float* Bb = Bs + (buf) * BS_STAGE;                              \
        uint32_t af[2][4][4], bf[2][4][2];                                    \
        LOADFRAG(0, 0);                                                       \
        _Pragma("unroll")                                                     \
        for (int kk = 0; kk < 4; kk++) {                                      \
            if (kk < 3) LOADFRAG(kk + 1, (kk + 1) & 1);                       \
            const int s = kk & 1;                                             \
            _Pragma("unroll")                                                 \
            for (int mt = 0; mt < 4; mt++)                                    \
                _Pragma("unroll")                                             \
                for (int nt = 0; nt < 4; nt++)                                \
                    MMA_TF32(acc[mt][nt], af[s][mt], bf[s][nt]);              \
        }                                                                     \
    }

    LOADG(0);
    STORES(0);
    __syncthreads();
    for (int ks = 0; ks < 64; ks++) {
        const int cur = ks & 1;
        if (ks < 63) { LOADG(ks + 1); }
        COMPUTE(cur);
        if (ks < 63) { STORES(cur ^ 1); }
        __syncthreads();
    }

#pragma unroll
    for (int mt = 0; mt < 4; mt++) {
#pragma unroll
        for (int nt = 0; nt < 4; nt++) {
            int r  = row0 + warp_m * 64 + mt * 16 + g;
            int cc = col0 + warp_n * 32 + nt * 8 + tig * 2;
            *(float2*)(C + (size_t)r * C_DIM + cc) =
                make_float2(acc[mt][nt][0], acc[mt][nt][1]);
            *(float2*)(C + (size_t)(r + 8) * C_DIM + cc) =
                make_float2(acc[mt][nt][2], acc[mt][nt][3]);
        }
    }
#undef LOADG
#undef STORES
#undef LOADFRAG
#undef COMPUTE
}

// ---------------- row squared norms ------------------------------------------
__global__ void rowsq_kernel(const float* __restrict__ xf, float* __restrict__ sq) {
    int row = blockIdx.x, tid = threadIdx.x;
    const float* x = xf + (size_t)row * C_DIM;
    float s = 0.f;
    for (int c = tid; c < C_DIM; c += 256) { float v = x[c]; s = fmaf(v, v, s); }
    for (int off = 16; off; off >>= 1) s += __shfl_xor_sync(0xffffffffu, s, off);
    __shared__ float r[8];
    if ((tid & 31) == 0) r[tid >> 5] = s;
    __syncthreads();
    if (tid == 0) { float t = 0.f; for (int w = 0; w < 8; w++) t += r[w]; sq[row] = t; }
}

// ---------------- pairwise distance: symmetric pair tiles 64x64, 256 thr -----
// CTA computes tile (bi, bj), bi <= bj (136 CTAs) with 256 threads (2 warps/
// SMSP keeps the FFMA issue pipe fed), 4x4 acc/thread, and writes the mirror
// tile too (values bit-identical: same sequential-k fma chain, a+b commutes).
__global__ __launch_bounds__(256) void dist_kernel(
    const float* __restrict__ xf, const float* __restrict__ sq,
    float* __restrict__ D) {
    __shared__ float As[16][64];
    __shared__ float Bs[16][64];
    int bb = blockIdx.x, bi = 0;
    while (bb >= 16 - bi) { bb -= 16 - bi; bi++; }
    const int bj = bi + bb;
    const int r0 = bi * 64, c0 = bj * 64;
    const int tid = threadIdx.x;
    const int am = tid >> 2, ak = (tid & 3) << 2;   // row 0..63, k 0/4/8/12
    const int ty = tid >> 4, tx = tid & 15;

    float4 a0, b0;
    a0 = *(const float4*)(xf + (size_t)(r0 + am) * C_DIM + ak);
    b0 = *(const float4*)(xf + (size_t)(c0 + am) * C_DIM + ak);
    float acc[4][4] = {};

#define DS_STORE()                                                            \
    {                                                                         \
        As[ak + 0][am] = a0.x; As[ak + 1][am] = a0.y;                         \
        As[ak + 2][am] = a0.z; As[ak + 3][am] = a0.w;                         \
        Bs[ak + 0][am] = b0.x; Bs[ak + 1][am] = b0.y;                         \
        Bs[ak + 2][am] = b0.z; Bs[ak + 3][am] = b0.w;                         \
    }
#define DS_COMPUTE()                                                          \
    _Pragma("unroll")                                                         \
    for (int kt = 0; kt < 16; kt++) {                                         \
        float af[4], bf[4];                                                   \
        *(float4*)&af[0] = *(const float4*)&As[kt][ty * 4];                   \
        *(float4*)&bf[0] = *(const float4*)&Bs[kt][tx * 4];                   \
        _Pragma("unroll")                                                     \
        for (int i = 0; i < 4; i++)                                           \
            _Pragma("unroll")                                                 \
            for (int j = 0; j < 4; j++)                                       \
                acc[i][j] = fmaf(af[i], bf[j], acc[i][j]);                    \
    }

    DS_STORE();
    __syncthreads();
    for (int k0 = 16; k0 < C_DIM; k0 += 16) {
        a0 = *(const float4*)(xf + (size_t)(r0 + am) * C_DIM + k0 + ak);
        b0 = *(const float4*)(xf + (size_t)(c0 + am) * C_DIM + k0 + ak);
        DS_COMPUTE();
        __syncthreads();
        DS_STORE();
        __syncthreads();
    }
    DS_COMPUTE();

#pragma unroll
    for (int i = 0; i < 4; i++) {
        int r = r0 + ty * 4 + i;
        float sqr = sq[r];
        float4 o;
        int c = c0 + tx * 4;
        o.x = sqrtf(fmaxf(sqr + sq[c + 0] - 2.f * acc[i][0], 0.f));
        o.y = sqrtf(fmaxf(sqr + sq[c + 1] - 2.f * acc[i][1], 0.f));
        o.z = sqrtf(fmaxf(sqr + sq[c + 2] - 2.f * acc[i][2], 0.f));
        o.w = sqrtf(fmaxf(sqr + sq[c + 3] - 2.f * acc[i][3], 0.f));
        *(float4*)(D + (size_t)r * N_NODES + c) = o;
        if (bi != bj) {
            D[(size_t)(c + 0) * N_NODES + r] = o.x;
            D[(size_t)(c + 1) * N_NODES + r] = o.y;
            D[(size_t)(c + 2) * N_NODES + r] = o.z;
            D[(size_t)(c + 3) * N_NODES + r] = o.w;
        }
    }
#undef DS_STORE
#undef DS_COMPUTE
}

// ---------------- kNN: 8 smallest per row (diag excluded), redux merge -------
__global__ void knn_kernel(const float* __restrict__ D, int* __restrict__ neigh) {
    int gw = (blockIdx.x * blockDim.x + threadIdx.x) >> 5;
    int lane = threadIdx.x & 31;
    if (gw >= N_NODES) return;
    const float* row = D + (size_t)gw * N_NODES;
    float val[8]; int idx[8];
#pragma unroll
    for (int r = 0; r < 8; r++) { val[r] = __int_as_float(0x7f800000); idx[r] = 0; }
    for (int j = lane; j < N_NODES; j += 32) {
        if (j == gw) continue;
        float v = row[j];
        if (v < val[7]) {
            val[7] = v; idx[7] = j;
#pragma unroll
            for (int p = 7; p > 0; p--) {
                if (val[p] < val[p - 1]) {
                    float tv = val[p]; val[p] = val[p - 1]; val[p - 1] = tv;
                    int   ti = idx[p]; idx[p] = idx[p - 1]; idx[p - 1] = ti;
                }
            }
        }
    }
    int ptr = 0;
#pragma unroll
    for (int r = 0; r < 8; r++) {
        unsigned vb = (ptr < 8) ? __float_as_uint(val[ptr]) : 0x7f800000u;
        unsigned vm = __reduce_min_sync(0xffffffffu, vb);
        unsigned mi = (ptr < 8 && vb == vm) ? (unsigned)idx[ptr] : 0x7fffffffu;
        unsigned im = __reduce_min_sync(0xffffffffu, mi);
        if (lane == 0) neigh[gw * KNB + r] = (int)im;
        if (ptr < 8 && vb == vm && (unsigned)idx[ptr] == im) ptr++;
    }
}

// ---------------- sequential k-means: 8 warps, 1 barrier/step ----------------
__global__ __launch_bounds__(256) void kmeans_kernel(
    const float* __restrict__ D, const int* __restrict__ perm,
    int* __restrict__ assign_out) {
    __shared__ float S[KC * N_NODES];       // 32KB, owner-thread only
    __shared__ float Drow_sh[2][N_NODES];   // 8KB, parity double-buffered
    __shared__ int   sperm[N_NODES];        // 4KB, read-only after init
    __shared__ u64   red[2][8];             // parity double-buffered
    const int t = threadIdx.x;
    const int lane = t & 31;
    const int wid = t >> 5;
    const float INF = __int_as_float(0x7f800000);
    const unsigned FULL = 0xffffffffu;

    for (int i = t; i < N_NODES; i += 256) sperm[i] = perm[i];
    __syncthreads();
    int mycent = (lane < KC) ? sperm[lane] : 0;   // replicated in every warp
    for (int c = 0; c < KC; c++) {
        const float* row = D + (size_t)sperm[c] * N_NODES;
#pragma unroll
        for (int j = 0; j < 4; j++)
            S[c * N_NODES + j * 256 + t] = row[j * 256 + t];
    }
    unsigned nib = 0u;
    for (int c = 0; c < KC; c++) {
        int p = sperm[c];
        if ((p & 255) == t) nib |= (unsigned)(c + 1) << ((p >> 8) * 4);
    }
    float cur[4], buf[2][4];
    {
        const float* r0 = D + (size_t)sperm[KC] * N_NODES;
        const float* r1 = D + (size_t)sperm[KC + 1] * N_NODES;
#pragma unroll
        for (int j = 0; j < 4; j++) {
            cur[j] = r0[j * 256 + t];
            Drow_sh[0][j * 256 + t] = cur[j];
            buf[1][j] = r1[j * 256 + t];
        }
    }
    int c_prev = -1;   // warp-uniform
    __syncthreads();

    for (int step = 0; step < NSTEPS; step++) {
        const int ni = sperm[KC + step];
        const int rb = step & 1;
        const int wb = rb ^ 1;
        // depth-2 prefetch (row for step+2 into buf[rb])
        {
            int nn = step + 2;
            if (nn >= NSTEPS) nn = NSTEPS - 1;
            const float* prow = D + (size_t)sperm[KC + nn] * N_NODES;
#pragma unroll
            for (int j = 0; j < 4; j++) buf[rb][j] = prow[j * 256 + t];
        }
        // finalize previous step's centroid (redundant in all 8 warps)
        if (step > 0) {
            u64 rv = (lane < 8) ? red[wb][lane] : ~0ull;
            unsigned hv = (unsigned)(rv >> 32);
            unsigned hm = __reduce_min_sync(FULL, hv);
            unsigned cand = (hv == hm) ? (unsigned)(rv & 0xffffffffull) : 0xffffffffu;
            unsigned newc = __reduce_min_sync(FULL, cand);
            if (lane == c_prev) mycent = (int)newc;
        }
        // select nearest centroid for ni (redundant; first-index tiebreak)
        unsigned cb = (lane < KC) ? __float_as_uint(Drow_sh[rb][mycent]) : 0x7f800000u;
        unsigned cm = __reduce_min_sync(FULL, cb);
        unsigned cmask = __ballot_sync(FULL, cb == cm);
        const int c = __ffs(cmask) - 1;
        c_prev = c;
        const unsigned tgt = (unsigned)(c + 1);
        // S[c] += Drow; masked min (argmin of S over members == argmin of mean)
        float* Sc = S + c * N_NODES;
        float vv[4];
#pragma unroll
        for (int j = 0; j < 4; j++) {
            float s = Sc[j * 256 + t] + cur[j];
            Sc[j * 256 + t] = s;
            bool memb = (((nib >> (j * 4)) & 15u) == tgt) | ((j * 256 + t) == ni);
            vv[j] = memb ? s : INF;
        }
        float m0 = fminf(vv[0], vv[2]), m1 = fminf(vv[1], vv[3]);
        const float minv = fminf(m0, m1);
        unsigned msk = 0u;
#pragma unroll
        for (int j = 0; j < 4; j++) msk |= (vv[j] == minv) ? (1u << j) : 0u;
        const int besti = (__ffs(msk) - 1) * 256 + t;
        unsigned bb = __float_as_uint(minv);
        unsigned bm = __reduce_min_sync(FULL, bb);
        unsigned cand2 = (bb == bm) ? (unsigned)besti : 0xffffffffu;
        unsigned im = __reduce_min_sync(FULL, cand2);
        if (lane == 0) red[rb][wid] = ((u64)bm << 32) | im;
        if ((ni & 255) == t) nib |= tgt << ((ni >> 8) * 4);
#pragma unroll
        for (int j = 0; j < 4; j++) {
            float v = buf[wb][j];
            Drow_sh[wb][j * 256 + t] = v;
            cur[j] = v;
        }
        __syncthreads();
    }
#pragma unroll
    for (int j = 0; j < 4; j++)
        assign_out[j * 256 + t] = (int)((nib >> (j * 4)) & 15u) - 1;
}

// ---------------- E[e] = sum_{v in neigh(e)} xf[v] ---------------------------
__global__ void agg_local_kernel(const float* __restrict__ xf, const int* __restrict__ neigh,
                                 float* __restrict__ E) {
    int e = blockIdx.x;
    int nb[KNB];
#pragma unroll
    for (int j = 0; j < KNB; j++) nb[j] = neigh[e * KNB + j];
    for (int c = threadIdx.x; c < C_DIM; c += 256) {
        float s = 0.f;
#pragma unroll
        for (int j = 0; j < KNB; j++) s += xf[(size_t)nb[j] * C_DIM + c];
        E[(size_t)e * C_DIM + c] = s;
    }
}

// ---------------- E[n+c] = sum_{assign[v]==c} xf[v] --------------------------
__global__ void agg_global_kernel(const float* __restrict__ xf, const int* __restrict__ assign_,
                                  float* __restrict__ E) {
    __shared__ int sa[N_NODES];
    int tid = threadIdx.x;
    for (int i = tid; i < N_NODES; i += 256) sa[i] = assign_[i];
    __syncthreads();
    int c = blockIdx.x;
    int col = blockIdx.y * 256 + tid;
    float s = 0.f;
    for (int i = 0; i < N_NODES; i++)
        if (sa[i] == c) s += xf[(size_t)i * C_DIM + col];
    E[(size_t)(N_NODES + c) * C_DIM + col] = s;
}

// ---------------- Y[v] = sum_{e: v in neigh(e)} X1[e] + X1[n+assign[v]] ------
__global__ void agg_out_kernel(const float* __restrict__ X1, const int* __restrict__ neigh,
                               const int* __restrict__ assign_, float* __restrict__ Y) {
    int v = blockIdx.x;
    __shared__ int list[N_NODES];
    __shared__ int cnt_s;
    int tid = threadIdx.x, lane = tid & 31, wid = tid >> 5;
    if (wid == 0) {
        int cnt = 0;
        for (int base = 0; base < N_NODES; base += 32) {
            int e = base + lane;
            const int4* p = (const int4*)(neigh + e * KNB);
            int4 q0 = p[0], q1 = p[1];
            bool m = (q0.x == v) | (q0.y == v) | (q0.z == v) | (q0.w == v) |
                     (q1.x == v) | (q1.y == v) | (q1.z == v) | (q1.w == v);
            unsigned msk = __ballot_sync(0xffffffffu, m);
            if (m) list[cnt + __popc(msk & ((1u << lane) - 1u))] = e;
            cnt += __popc(msk);
        }
        if (lane == 0) cnt_s = cnt;
    }
    __syncthreads();
    int cnt = cnt_s;
    int ge = N_NODES + assign_[v];
    float s[8];
#pragma unroll
    for (int w = 0; w < 8; w++) s[w] = X1[(size_t)ge * C_DIM + tid + w * 256];
    for (int t = 0; t < cnt; t++) {
        const float* xr = X1 + (size_t)list[t] * C_DIM;
#pragma unroll
        for (int w = 0; w < 8; w++) s[w] += xr[tid + w * 256];
    }
#pragma unroll
    for (int w = 0; w < 8; w++) Y[(size_t)v * C_DIM + tid + w * 256] = s[w];
}

// ---------------- host launcher ----------------------------------------------
extern "C" void kernel_launch(void* const* d_in, const int* in_sizes, int n_in,
                              void* d_out, int out_size) {
    const float* x0  = (const float*)d_in[0];
    const float* wfc = (const float*)d_in[1];
    const float* bfc = (const float*)d_in[2];
    const float* w1  = (const float*)d_in[3];
    const float* w2  = (const float*)d_in[4];
    float* out = (float*)d_out;

    float *xf, *sq, *D, *E, *X1, *Y;
    int *neigh, *perm, *assign_;
    cudaGetSymbolAddress((void**)&xf,      g_xf);
    cudaGetSymbolAddress((void**)&sq,      g_sq);
    cudaGetSymbolAddress((void**)&D,       g_D);
    cudaGetSymbolAddress((void**)&neigh,   g_neigh);
    cudaGetSymbolAddress((void**)&perm,    g_perm);
    cudaGetSymbolAddress((void**)&assign_, g_assign);
    cudaGetSymbolAddress((void**)&E,       g_E);
    cudaGetSymbolAddress((void**)&X1,      g_X1);
    cudaGetSymbolAddress((void**)&Y,       g_Y);

    const size_t dynsmem = (2 * AS_STAGE + 2 * BS_STAGE) * sizeof(float);  // 69632
    cudaFuncSetAttribute(mma_gemm_kernel,
                         cudaFuncAttributeMaxDynamicSharedMemorySize, (int)dynsmem);

    perm_kernel<<<1, 1024>>>(perm);
    sgemm_kernel<<<dim3(C_DIM / 128, N_NODES / 128), 256>>>(x0, wfc, bfc, xf,
                                                            N_NODES, C_DIM, C_DIM);
    rowsq_kernel<<<N_NODES, 256>>>(xf, sq);
    dist_kernel<<<136, 256>>>(xf, sq, D);
    knn_kernel<<<N_NODES / 8, 256>>>(D, neigh);
    kmeans_kernel<<<1, 256>>>(D, perm, assign_);
    agg_local_kernel<<<N_NODES, 256>>>(xf, neigh, E);
    agg_global_kernel<<<dim3(KC, C_DIM / 256), 256>>>(xf, assign_, E);
    mma_gemm_kernel<<<dim3(C_DIM / 128, E_PAD / 128), 256, dynsmem>>>(E, w1, X1);
    agg_out_kernel<<<N_NODES, 256>>>(X1, neigh, assign_, Y);
    mma_gemm_kernel<<<dim3(C_DIM / 128, N_NODES / 128), 256, dynsmem>>>(Y, w2, out);
}

// round 15
// speedup vs baseline: 1.1568x; 1.0522x over previous
#include <cuda_runtime.h>
#include <cstdint>
#include <cstddef>

#define N_NODES 1024
#define C_DIM   2048
#define KNB     8
#define KC      8
#define N_EDGES (N_NODES + KC)
#define NSTEPS  (N_NODES - KC)
#define E_PAD   1152   // padded edge-row count (9 * 128)

typedef unsigned long long u64;

// ---------------- scratch (static __device__, zero-initialized) --------------
__device__ float g_xf[N_NODES * C_DIM];
__device__ float g_sq[N_NODES];
__device__ float g_D[N_NODES * N_NODES];
__device__ int   g_neigh[N_NODES * KNB];
__device__ int   g_perm[N_NODES];
__device__ int   g_assign[N_NODES];
__device__ float g_E[E_PAD * C_DIM];    // rows 1032..1151 stay zero
__device__ float g_X1[E_PAD * C_DIM];
__device__ float g_Y[N_NODES * C_DIM];

// ---------------- helpers ----------------------------------------------------
__device__ __forceinline__ float to_tf32(float x) {
    uint32_t r;
    asm("cvt.rna.tf32.f32 %0, %1;" : "=r"(r) : "f"(x));
    return __uint_as_float(r);
}

#define MMA_TF32(d, a, b)                                                     \
    asm volatile(                                                             \
        "mma.sync.aligned.m16n8k8.row.col.f32.tf32.tf32.f32 "                 \
        "{%0,%1,%2,%3}, {%4,%5,%6,%7}, {%8,%9}, {%0,%1,%2,%3};"               \
        : "+f"((d)[0]), "+f"((d)[1]), "+f"((d)[2]), "+f"((d)[3])              \
        : "r"((a)[0]), "r"((a)[1]), "r"((a)[2]), "r"((a)[3]),                 \
          "r"((b)[0]), "r"((b)[1]))

// ---------------- threefry-2x32 (20 rounds) ----------------------------------
__device__ __forceinline__ void threefry2x32(unsigned k0, unsigned k1,
                                             unsigned& x0, unsigned& x1) {
    unsigned ks2 = k0 ^ k1 ^ 0x1BD11BDAu;
    x0 += k0; x1 += k1;
#define TF_R(r) { x0 += x1; x1 = (x1 << (r)) | (x1 >> (32 - (r))); x1 ^= x0; }
    TF_R(13) TF_R(15) TF_R(26) TF_R(6)
    x0 += k1;  x1 += ks2 + 1u;
    TF_R(17) TF_R(29) TF_R(16) TF_R(24)
    x0 += ks2; x1 += k0 + 2u;
    TF_R(13) TF_R(15) TF_R(26) TF_R(6)
    x0 += k0;  x1 += k1 + 3u;
    TF_R(17) TF_R(29) TF_R(16) TF_R(24)
    x0 += k1;  x1 += ks2 + 4u;
    TF_R(13) TF_R(15) TF_R(26) TF_R(6)
    x0 += ks2; x1 += k0 + 5u;
#undef TF_R
}

__global__ void perm_kernel(int* __restrict__ perm) {
    __shared__ u64 keys[N_NODES];
    int tid = threadIdx.x;
    unsigned s0, s1;
    { unsigned a0 = 0u, a1 = 1u; threefry2x32(0u, 42u, a0, a1); s0 = a0; s1 = a1; }
    if (tid < 512) {
        unsigned x0 = 0u, x1 = (unsigned)tid;
        threefry2x32(s0, s1, x0, x1);
        keys[tid] = ((u64)(x0 ^ x1) << 32) | (unsigned)tid;
        unsigned y0 = 0u, y1 = (unsigned)(tid + 512);
        threefry2x32(s0, s1, y0, y1);
        keys[tid + 512] = ((u64)(y0 ^ y1) << 32) | (unsigned)(tid + 512);
    }
    __syncthreads();
    for (int k = 2; k <= N_NODES; k <<= 1) {
        for (int j = k >> 1; j > 0; j >>= 1) {
            int ixj = tid ^ j;
            if (ixj > tid) {
                u64 a = keys[tid], b = keys[ixj];
                bool up = ((tid & k) == 0);
                if ((a > b) == up) { keys[tid] = b; keys[ixj] = a; }
            }
            __syncthreads();
        }
    }
    perm[tid] = (int)(keys[tid] & 0xffffffffull);
}

// ---------------- fp32 SGEMM (GEMM1): 128x128, 8x8/thread, smem 2-buffer -----
__global__ __launch_bounds__(256) void sgemm_kernel(
    const float* __restrict__ A, const float* __restrict__ B,
    const float* __restrict__ bias, float* __restrict__ C,
    int M, int N, int K) {
    __shared__ float As[2][16][128];
    __shared__ float Bs[2][16][128];
    const int tid  = threadIdx.x;
    const int row0 = blockIdx.y * 128;
    const int col0 = blockIdx.x * 128;
    const int am = tid >> 2, ak = (tid & 3) << 2;
    const int bk = tid >> 5, bn = (tid & 31) << 2;
    const int ty = tid >> 4, tx = tid & 15;
    const float4 z4 = make_float4(0.f, 0.f, 0.f, 0.f);

    float4 a0, a1, b0, b1;
    {
        int r = row0 + am;
        a0 = (r      < M) ? *(const float4*)(A + (size_t)r        * K + ak) : z4;
        a1 = (r + 64 < M) ? *(const float4*)(A + (size_t)(r + 64) * K + ak) : z4;
        b0 = *(const float4*)(B + (size_t)bk       * N + col0 + bn);
        b1 = *(const float4*)(B + (size_t)(bk + 8) * N + col0 + bn);
    }
    float acc[8][8] = {};

#define STORE_TILES(s)                                                        \
    {                                                                         \
        As[s][ak + 0][am] = a0.x; As[s][ak + 1][am] = a0.y;                   \
        As[s][ak + 2][am] = a0.z; As[s][ak + 3][am] = a0.w;                   \
        As[s][ak + 0][am + 64] = a1.x; As[s][ak + 1][am + 64] = a1.y;         \
        As[s][ak + 2][am + 64] = a1.z; As[s][ak + 3][am + 64] = a1.w;         \
        *(float4*)&Bs[s][bk][bn]     = b0;                                    \
        *(float4*)&Bs[s][bk + 8][bn] = b1;                                    \
    }
#define COMPUTE_TILE(s)                                                       \
    _Pragma("unroll")                                                         \
    for (int kt = 0; kt < 16; kt++) {                                         \
        float af[8], bf[8];                                                   \
        *(float4*)&af[0] = *(const float4*)&As[s][kt][ty * 8];                \
        *(float4*)&af[4] = *(const float4*)&As[s][kt][ty * 8 + 4];            \
        *(float4*)&bf[0] = *(const float4*)&Bs[s][kt][tx * 8];                \
        *(float4*)&bf[4] = *(const float4*)&Bs[s][kt][tx * 8 + 4];            \
        _Pragma("unroll")                                                     \
        for (int i = 0; i < 8; i++)                                           \
            _Pragma("unroll")                                                 \
            for (int j = 0; j < 8; j++)                                       \
                acc[i][j] = fmaf(af[i], bf[j], acc[i][j]);                    \
    }

    STORE_TILES(0);
    __syncthreads();
    const int NSTAGE = K / 16;
    for (int ks = 0; ks < NSTAGE; ks++) {
        const int cur = ks & 1;
        if (ks + 1 < NSTAGE) {
            int k0 = (ks + 1) * 16;
            int r = row0 + am;
            a0 = (r      < M) ? *(const float4*)(A + (size_t)r        * K + k0 + ak) : z4;
            a1 = (r + 64 < M) ? *(const float4*)(A + (size_t)(r + 64) * K + k0 + ak) : z4;
            b0 = *(const float4*)(B + (size_t)(k0 + bk)     * N + col0 + bn);
            b1 = *(const float4*)(B + (size_t)(k0 + bk + 8) * N + col0 + bn);
        }
        COMPUTE_TILE(cur);
        if (ks + 1 < NSTAGE) STORE_TILES(cur ^ 1);
        __syncthreads();
    }

    float4 bias0 = z4, bias1 = z4;
    if (bias) {
        bias0 = *(const float4*)(bias + col0 + tx * 8);
        bias1 = *(const float4*)(bias + col0 + tx * 8 + 4);
    }
#pragma unroll
    for (int i = 0; i < 8; i++) {
        int r = row0 + ty * 8 + i;
        if (r < M) {
            float4 o0 = make_float4(acc[i][0] + bias0.x, acc[i][1] + bias0.y,
                                    acc[i][2] + bias0.z, acc[i][3] + bias0.w);
            float4 o1 = make_float4(acc[i][4] + bias1.x, acc[i][5] + bias1.y,
                                    acc[i][6] + bias1.z, acc[i][7] + bias1.w);
            *(float4*)(C + (size_t)r * N + col0 + tx * 8)     = o0;
            *(float4*)(C + (size_t)r * N + col0 + tx * 8 + 4) = o1;
        }
    }
#undef STORE_TILES
#undef COMPUTE_TILE
}

// ---------------- tf32 mma.sync GEMM: C[M,2048] = A[M,2048] @ B[2048,2048] ---
#define AS_STRIDE 36
#define AS_STAGE  (128 * AS_STRIDE)
#define BS_STAGE  (32 * 128)

__global__ __launch_bounds__(256) void mma_gemm_kernel(
    const float* __restrict__ A, const float* __restrict__ B,
    float* __restrict__ C) {
    extern __shared__ float sm[];
    float* As = sm;                    // [2][128][36]
    float* Bs = sm + 2 * AS_STAGE;     // [2][32][128]
    const int tid  = threadIdx.x;
    const int lane = tid & 31, wid = tid >> 5;
    const int warp_m = wid >> 2, warp_n = wid & 3;
    const int g = lane >> 2, tig = lane & 3;
    const int row0 = blockIdx.y * 128, col0 = blockIdx.x * 128;

    float acc[4][4][4] = {};
    float4 ar[4], br[4];

#define LOADG(ks)                                                             \
    _Pragma("unroll")                                                         \
    for (int i = 0; i < 4; i++) {                                             \
        int ch = tid * 4 + i;                                                 \
        ar[i] = *(const float4*)(A + (size_t)(row0 + (ch >> 3)) * C_DIM       \
                                 + (ks) * 32 + (ch & 7) * 4);                 \
        br[i] = *(const float4*)(B + (size_t)((ks) * 32 + (ch >> 5)) * C_DIM  \
                                 + col0 + (ch & 31) * 4);                     \
    }

#define STORES(buf)                                                           \
    {                                                                         \
        float* Ab = As + (buf) * AS_STAGE;                                    \
        float* Bb = Bs + (buf) * BS_STAGE;                                    \
        _Pragma("unroll")                                                     \
        for (int i = 0; i < 4; i++) {                                         \
            int ch = tid * 4 + i;                                             \
            float4 v = ar[i];                                                 \
            v.x = to_tf32(v.x); v.y = to_tf32(v.y);                           \
            v.z = to_tf32(v.z); v.w = to_tf32(v.w);                           \
            *(float4*)(Ab + (ch >> 3) * AS_STRIDE + (ch & 7) * 4) = v;        \
            float4 w = br[i];                                                 \
            w.x = to_tf32(w.x); w.y = to_tf32(w.y);                           \
            w.z = to_tf32(w.z); w.w = to_tf32(w.w);                           \
            int kb = ch >> 5, n4 = ch & 31;                                   \
            *(float4*)(Bb + kb * 128 + ((n4 * 4) ^ ((kb & 3) << 3))) = w;     \
        }                                                                     \
    }

#define LOADFRAG(kk, s)                                                       \
    {                                                                         \
        const int k1 = (kk) * 8 + tig, k2 = (kk) * 8 + tig + 4;               \
        _Pragma("unroll")                                                     \
        for (int mt = 0; mt < 4; mt++) {                                      \
            int m0 = warp_m * 64 + mt * 16;                                   \
            af[s][mt][0] = __float_as_uint(Ab[(m0 + g)     * AS_STRIDE + k1]); \
            af[s][mt][1] = __float_as_uint(Ab[(m0 + 8 + g) * AS_STRIDE + k1]); \
            af[s][mt][2] = __float_as_uint(Ab[(m0 + g)     * AS_STRIDE + k2]); \
            af[s][mt][3] = __float_as_uint(Ab[(m0 + 8 + g) * AS_STRIDE + k2]); \
        }                                                                     \
        _Pragma("unroll")                                                     \
        for (int nt = 0; nt < 4; nt++) {                                      \
            int n0 = warp_n * 32 + nt * 8;                                    \
            bf[s][nt][0] = __float_as_uint(Bb[k1 * 128 + ((n0 + g) ^ (tig << 3))]); \
            bf[s][nt][1] = __float_as_uint(Bb[k2 * 128 + ((n0 + g) ^ (tig << 3))]); \
        }                                                                     \
    }

#define COMPUTE(buf)                                                          \
    {                                                                         \
        const float* Ab = As + (buf) * AS_STAGE;                              \
        const float* Bb = Bs + (buf) * BS_STAGE;                              \
        uint32_t af[2][4][4], bf[2][4][2];                                    \
        LOADFRAG(0, 0);                                                       \
        _Pragma("unroll")                                                     \
        for (int kk = 0; kk < 4; kk++) {                                      \
            if (kk < 3) LOADFRAG(kk + 1, (kk + 1) & 1);                       \
            const int s = kk & 1;                                             \
            _Pragma("unroll")                                                 \
            for (int mt = 0; mt < 4; mt++)                                    \
                _Pragma("unroll")                                             \
                for (int nt = 0; nt < 4; nt++)                                \
                    MMA_TF32(acc[mt][nt], af[s][mt], bf[s][nt]);              \
        }                                                                     \
    }

    LOADG(0);
    STORES(0);
    __syncthreads();
    for (int ks = 0; ks < 64; ks++) {
        const int cur = ks & 1;
        if (ks < 63) { LOADG(ks + 1); }
        COMPUTE(cur);
        if (ks < 63) { STORES(cur ^ 1); }
        __syncthreads();
    }

#pragma unroll
    for (int mt = 0; mt < 4; mt++) {
#pragma unroll
        for (int nt = 0; nt < 4; nt++) {
            int r  = row0 + warp_m * 64 + mt * 16 + g;
            int cc = col0 + warp_n * 32 + nt * 8 + tig * 2;
            *(float2*)(C + (size_t)r * C_DIM + cc) =
                make_float2(acc[mt][nt][0], acc[mt][nt][1]);
            *(float2*)(C + (size_t)(r + 8) * C_DIM + cc) =
                make_float2(acc[mt][nt][2], acc[mt][nt][3]);
        }
    }
#undef LOADG
#undef STORES
#undef LOADFRAG
#undef COMPUTE
}

// ---------------- row squared norms ------------------------------------------
__global__ void rowsq_kernel(const float* __restrict__ xf, float* __restrict__ sq) {
    int row = blockIdx.x, tid = threadIdx.x;
    const float* x = xf + (size_t)row * C_DIM;
    float s = 0.f;
    for (int c = tid; c < C_DIM; c += 256) { float v = x[c]; s = fmaf(v, v, s); }
    for (int off = 16; off; off >>= 1) s += __shfl_xor_sync(0xffffffffu, s, off);
    __shared__ float r[8];
    if ((tid & 31) == 0) r[tid >> 5] = s;
    __syncthreads();
    if (tid == 0) { float t = 0.f; for (int w = 0; w < 8; w++) t += r[w]; sq[row] = t; }
}

// ---------------- pairwise distance: symmetric 64x64 pair tiles, 2-buffer ----
__global__ __launch_bounds__(256) void dist_kernel(
    const float* __restrict__ xf, const float* __restrict__ sq,
    float* __restrict__ D) {
    __shared__ float As[2][16][64];
    __shared__ float Bs[2][16][64];
    int bb = blockIdx.x, bi = 0;
    while (bb >= 16 - bi) { bb -= 16 - bi; bi++; }
    const int bj = bi + bb;
    const int r0 = bi * 64, c0 = bj * 64;
    const int tid = threadIdx.x;
    const int am = tid >> 2, ak = (tid & 3) << 2;   // row 0..63, k 0/4/8/12
    const int ty = tid >> 4, tx = tid & 15;

    float4 a0, b0;
    a0 = *(const float4*)(xf + (size_t)(r0 + am) * C_DIM + ak);
    b0 = *(const float4*)(xf + (size_t)(c0 + am) * C_DIM + ak);
    float acc[4][4] = {};

#define DS_STORE(s)                                                           \
    {                                                                         \
        As[s][ak + 0][am] = a0.x; As[s][ak + 1][am] = a0.y;                   \
        As[s][ak + 2][am] = a0.z; As[s][ak + 3][am] = a0.w;                   \
        Bs[s][ak + 0][am] = b0.x; Bs[s][ak + 1][am] = b0.y;                   \
        Bs[s][ak + 2][am] = b0.z; Bs[s][ak + 3][am] = b0.w;                   \
    }
#define DS_COMPUTE(s)                                                         \
    _Pragma("unroll")                                                         \
    for (int kt = 0; kt < 16; kt++) {                                         \
        float af[4], bf[4];                                                   \
        *(float4*)&af[0] = *(const float4*)&As[s][kt][ty * 4];                \
        *(float4*)&bf[0] = *(const float4*)&Bs[s][kt][tx * 4];                \
        _Pragma("unroll")                                                     \
        for (int i = 0; i < 4; i++)                                           \
            _Pragma("unroll")                                                 \
            for (int j = 0; j < 4; j++)                                       \
                acc[i][j] = fmaf(af[i], bf[j], acc[i][j]);                    \
    }

    DS_STORE(0);
    __syncthreads();
    for (int ks = 0; ks < C_DIM / 16; ks++) {
        const int cur = ks & 1;
        if (ks + 1 < C_DIM / 16) {
            int k0 = (ks + 1) * 16;
            a0 = *(const float4*)(xf + (size_t)(r0 + am) * C_DIM + k0 + ak);
            b0 = *(const float4*)(xf + (size_t)(c0 + am) * C_DIM + k0 + ak);
        }
        DS_COMPUTE(cur);
        if (ks + 1 < C_DIM / 16) DS_STORE(cur ^ 1);
        __syncthreads();
    }

#pragma unroll
    for (int i = 0; i < 4; i++) {
        int r = r0 + ty * 4 + i;
        float sqr = sq[r];
        float4 o;
        int c = c0 + tx * 4;
        o.x = sqrtf(fmaxf(sqr + sq[c + 0] - 2.f * acc[i][0], 0.f));
        o.y = sqrtf(fmaxf(sqr + sq[c + 1] - 2.f * acc[i][1], 0.f));
        o.z = sqrtf(fmaxf(sqr + sq[c + 2] - 2.f * acc[i][2], 0.f));
        o.w = sqrtf(fmaxf(sqr + sq[c + 3] - 2.f * acc[i][3], 0.f));
        *(float4*)(D + (size_t)r * N_NODES + c) = o;
        if (bi != bj) {
            D[(size_t)(c + 0) * N_NODES + r] = o.x;
            D[(size_t)(c + 1) * N_NODES + r] = o.y;
            D[(size_t)(c + 2) * N_NODES + r] = o.z;
            D[(size_t)(c + 3) * N_NODES + r] = o.w;
        }
    }
#undef DS_STORE
#undef DS_COMPUTE
}

// ---------------- kNN: 8 smallest per row (diag excluded), redux merge -------
__global__ void knn_kernel(const float* __restrict__ D, int* __restrict__ neigh) {
    int gw = (blockIdx.x * blockDim.x + threadIdx.x) >> 5;
    int lane = threadIdx.x & 31;
    if (gw >= N_NODES) return;
    const float* row = D + (size_t)gw * N_NODES;
    float val[8]; int idx[8];
#pragma unroll
    for (int r = 0; r < 8; r++) { val[r] = __int_as_float(0x7f800000); idx[r] = 0; }
    for (int j = lane; j < N_NODES; j += 32) {
        if (j == gw) continue;
        float v = row[j];
        if (v < val[7]) {
            val[7] = v; idx[7] = j;
#pragma unroll
            for (int p = 7; p > 0; p--) {
                if (val[p] < val[p - 1]) {
                    float tv = val[p]; val[p] = val[p - 1]; val[p - 1] = tv;
                    int   ti = idx[p]; idx[p] = idx[p - 1]; idx[p - 1] = ti;
                }
            }
        }
    }
    int ptr = 0;
#pragma unroll
    for (int r = 0; r < 8; r++) {
        unsigned vb = (ptr < 8) ? __float_as_uint(val[ptr]) : 0x7f800000u;
        unsigned vm = __reduce_min_sync(0xffffffffu, vb);
        unsigned mi = (ptr < 8 && vb == vm) ? (unsigned)idx[ptr] : 0x7fffffffu;
        unsigned im = __reduce_min_sync(0xffffffffu, mi);
        if (lane == 0) neigh[gw * KNB + r] = (int)im;
        if (ptr < 8 && vb == vm && (unsigned)idx[ptr] == im) ptr++;
    }
}

// ---------------- sequential k-means: 8 warps, 1 barrier/step ----------------
__global__ __launch_bounds__(256) void kmeans_kernel(
    const float* __restrict__ D, const int* __restrict__ perm,
    int* __restrict__ assign_out) {
    __shared__ float S[KC * N_NODES];       // 32KB, owner-thread only
    __shared__ float Drow_sh[2][N_NODES];   // 8KB, parity double-buffered
    __shared__ int   sperm[N_NODES];        // 4KB, read-only after init
    __shared__ u64   red[2][8];             // parity double-buffered
    const int t = threadIdx.x;
    const int lane = t & 31;
    const int wid = t >> 5;
    const float INF = __int_as_float(0x7f800000);
    const unsigned FULL = 0xffffffffu;

    for (int i = t; i < N_NODES; i += 256) sperm[i] = perm[i];
    __syncthreads();
    int mycent = (lane < KC) ? sperm[lane] : 0;   // replicated in every warp
    for (int c = 0; c < KC; c++) {
        const float* row = D + (size_t)sperm[c] * N_NODES;
#pragma unroll
        for (int j = 0; j < 4; j++)
            S[c * N_NODES + j * 256 + t] = row[j * 256 + t];
    }
    unsigned nib = 0u;
    for (int c = 0; c < KC; c++) {
        int p = sperm[c];
        if ((p & 255) == t) nib |= (unsigned)(c + 1) << ((p >> 8) * 4);
    }
    float cur[4], buf[2][4];
    {
        const float* r0 = D + (size_t)sperm[KC] * N_NODES;
        const float* r1 = D + (size_t)sperm[KC + 1] * N_NODES;
#pragma unroll
        for (int j = 0; j < 4; j++) {
            cur[j] = r0[j * 256 + t];
            Drow_sh[0][j * 256 + t] = cur[j];
            buf[1][j] = r1[j * 256 + t];
        }
    }
    int c_prev = -1;   // warp-uniform
    __syncthreads();

    for (int step = 0; step < NSTEPS; step++) {
        const int ni = sperm[KC + step];
        const int rb = step & 1;
        const int wb = rb ^ 1;
        // depth-2 prefetch (row for step+2 into buf[rb])
        {
            int nn = step + 2;
            if (nn >= NSTEPS) nn = NSTEPS - 1;
            const float* prow = D + (size_t)sperm[KC + nn] * N_NODES;
#pragma unroll
            for (int j = 0; j < 4; j++) buf[rb][j] = prow[j * 256 + t];
        }
        // finalize previous step's centroid (redundant in all 8 warps)
        if (step > 0) {
            u64 rv = (lane < 8) ? red[wb][lane] : ~0ull;
            unsigned hv = (unsigned)(rv >> 32);
            unsigned hm = __reduce_min_sync(FULL, hv);
            unsigned cand = (hv == hm) ? (unsigned)(rv & 0xffffffffull) : 0xffffffffu;
            unsigned newc = __reduce_min_sync(FULL, cand);
            if (lane == c_prev) mycent = (int)newc;
        }
        // select nearest centroid for ni (redundant; first-index tiebreak)
        unsigned cb = (lane < KC) ? __float_as_uint(Drow_sh[rb][mycent]) : 0x7f800000u;
        unsigned cm = __reduce_min_sync(FULL, cb);
        unsigned cmask = __ballot_sync(FULL, cb == cm);
        const int c = __ffs(cmask) - 1;
        c_prev = c;
        const unsigned tgt = (unsigned)(c + 1);
        // S[c] += Drow; masked min (argmin of S over members == argmin of mean)
        float* Sc = S + c * N_NODES;
        float vv[4];
#pragma unroll
        for (int j = 0; j < 4; j++) {
            float s = Sc[j * 256 + t] + cur[j];
            Sc[j * 256 + t] = s;
            bool memb = (((nib >> (j * 4)) & 15u) == tgt) | ((j * 256 + t) == ni);
            vv[j] = memb ? s : INF;
        }
        float m0 = fminf(vv[0], vv[2]), m1 = fminf(vv[1], vv[3]);
        const float minv = fminf(m0, m1);
        unsigned msk = 0u;
#pragma unroll
        for (int j = 0; j < 4; j++) msk |= (vv[j] == minv) ? (1u << j) : 0u;
        const int besti = (__ffs(msk) - 1) * 256 + t;
        unsigned bb = __float_as_uint(minv);
        unsigned bm = __reduce_min_sync(FULL, bb);
        unsigned cand2 = (bb == bm) ? (unsigned)besti : 0xffffffffu;
        unsigned im = __reduce_min_sync(FULL, cand2);
        if (lane == 0) red[rb][wid] = ((u64)bm << 32) | im;
        if ((ni & 255) == t) nib |= tgt << ((ni >> 8) * 4);
#pragma unroll
        for (int j = 0; j < 4; j++) {
            float v = buf[wb][j];
            Drow_sh[wb][j * 256 + t] = v;
            cur[j] = v;
        }
        __syncthreads();
    }
#pragma unroll
    for (int j = 0; j < 4; j++)
        assign_out[j * 256 + t] = (int)((nib >> (j * 4)) & 15u) - 1;
}

// ---------------- E[e] = sum_{v in neigh(e)} xf[v] ---------------------------
__global__ void agg_local_kernel(const float* __restrict__ xf, const int* __restrict__ neigh,
                                 float* __restrict__ E) {
    int e = blockIdx.x;
    int nb[KNB];
#pragma unroll
    for (int j = 0; j < KNB; j++) nb[j] = neigh[e * KNB + j];
    for (int c = threadIdx.x; c < C_DIM; c += 256) {
        float s = 0.f;
#pragma unroll
        for (int j = 0; j < KNB; j++) s += xf[(size_t)nb[j] * C_DIM + c];
        E[(size_t)e * C_DIM + c] = s;
    }
}

// ---------------- E[n+c] = sum_{assign[v]==c} xf[v] --------------------------
__global__ void agg_global_kernel(const float* __restrict__ xf, const int* __restrict__ assign_,
                                  float* __restrict__ E) {
    __shared__ int sa[N_NODES];
    int tid = threadIdx.x;
    for (int i = tid; i < N_NODES; i += 256) sa[i] = assign_[i];
    __syncthreads();
    int c = blockIdx.x;
    int col = blockIdx.y * 256 + tid;
    float s = 0.f;
    for (int i = 0; i < N_NODES; i++)
        if (sa[i] == c) s += xf[(size_t)i * C_DIM + col];
    E[(size_t)(N_NODES + c) * C_DIM + col] = s;
}

// ---------------- Y[v] = sum_{e: v in neigh(e)} X1[e] + X1[n+assign[v]] ------
__global__ void agg_out_kernel(const float* __restrict__ X1, const int* __restrict__ neigh,
                               const int* __restrict__ assign_, float* __restrict__ Y) {
    int v = blockIdx.x;
    __shared__ int list[N_NODES];
    __shared__ int cnt_s;
    int tid = threadIdx.x, lane = tid & 31, wid = tid >> 5;
    if (wid == 0) {
        int cnt = 0;
        for (int base = 0; base < N_NODES; base += 32) {
            int e = base + lane;
            const int4* p = (const int4*)(neigh + e * KNB);
            int4 q0 = p[0], q1 = p[1];
            bool m = (q0.x == v) | (q0.y == v) | (q0.z == v) | (q0.w == v) |
                     (q1.x == v) | (q1.y == v) | (q1.z == v) | (q1.w == v);
            unsigned msk = __ballot_sync(0xffffffffu, m);
            if (m) list[cnt + __popc(msk & ((1u << lane) - 1u))] = e;
            cnt += __popc(msk);
        }
        if (lane == 0) cnt_s = cnt;
    }
    __syncthreads();
    int cnt = cnt_s;
    int ge = N_NODES + assign_[v];
    float s[8];
#pragma unroll
    for (int w = 0; w < 8; w++) s[w] = X1[(size_t)ge * C_DIM + tid + w * 256];
    for (int t = 0; t < cnt; t++) {
        const float* xr = X1 + (size_t)list[t] * C_DIM;
#pragma unroll
        for (int w = 0; w < 8; w++) s[w] += xr[tid + w * 256];
    }
#pragma unroll
    for (int w = 0; w < 8; w++) Y[(size_t)v * C_DIM + tid + w * 256] = s[w];
}

// ---------------- host launcher ----------------------------------------------
extern "C" void kernel_launch(void* const* d_in, const int* in_sizes, int n_in,
                              void* d_out, int out_size) {
    const float* x0  = (const float*)d_in[0];
    const float* wfc = (const float*)d_in[1];
    const float* bfc = (const float*)d_in[2];
    const float* w1  = (const float*)d_in[3];
    const float* w2  = (const float*)d_in[4];
    float* out = (float*)d_out;

    float *xf, *sq, *D, *E, *X1, *Y;
    int *neigh, *perm, *assign_;
    cudaGetSymbolAddress((void**)&xf,      g_xf);
    cudaGetSymbolAddress((void**)&sq,      g_sq);
    cudaGetSymbolAddress((void**)&D,       g_D);
    cudaGetSymbolAddress((void**)&neigh,   g_neigh);
    cudaGetSymbolAddress((void**)&perm,    g_perm);
    cudaGetSymbolAddress((void**)&assign_, g_assign);
    cudaGetSymbolAddress((void**)&E,       g_E);
    cudaGetSymbolAddress((void**)&X1,      g_X1);
    cudaGetSymbolAddress((void**)&Y,       g_Y);

    const size_t dynsmem = (2 * AS_STAGE + 2 * BS_STAGE) * sizeof(float);  // 69632
    cudaFuncSetAttribute(mma_gemm_kernel,
                         cudaFuncAttributeMaxDynamicSharedMemorySize, (int)dynsmem);

    perm_kernel<<<1, 1024>>>(perm);
    sgemm_kernel<<<dim3(C_DIM / 128, N_NODES / 128), 256>>>(x0, wfc, bfc, xf,
                                                            N_NODES, C_DIM, C_DIM);
    rowsq_kernel<<<N_NODES, 256>>>(xf, sq);
    dist_kernel<<<136, 256>>>(xf, sq, D);
    knn_kernel<<<N_NODES / 8, 256>>>(D, neigh);
    kmeans_kernel<<<1, 256>>>(D, perm, assign_);
    agg_local_kernel<<<N_NODES, 256>>>(xf, neigh, E);
    agg_global_kernel<<<dim3(KC, C_DIM / 256), 256>>>(xf, assign_, E);
    mma_gemm_kernel<<<dim3(C_DIM / 128, E_PAD / 128), 256, dynsmem>>>(E, w1, X1);
    agg_out_kernel<<<N_NODES, 256>>>(X1, neigh, assign_, Y);
    mma_gemm_kernel<<<dim3(C_DIM / 128, N_NODES / 128), 256, dynsmem>>>(Y, w2, out);
}